// round 9
// baseline (speedup 1.0000x reference)
#include <cuda_runtime.h>

// Problem constants (fixed per metadata)
#define EMAX 160000
#define NMAX 10000

// Scratch (device globals — allocation-free)
__device__ float g_ex[EMAX * 4];      // exp(score) per edge/head
__device__ float g_v[EMAX * 24];      // v per edge (m2*d2 = 24)
__device__ float g_denom[NMAX * 4];   // softmax denominator per node/head

// Packed fp32x2 FMA (Blackwell): d.lo += a.lo*b.lo ; d.hi += a.hi*b.hi
#define FMA_F32X2(d, a, b) \
    asm("fma.rn.f32x2 %0, %1, %2, %0;" : "+l"(d) : "l"(a), "l"(b))

// Shared memory layout (in floats)
#define OFF_W2S 0        // [768][64]  W2 original layout, quad-XOR swizzled rows
#define OFF_W1S 49152    // [64][32]   W1 original layout (k contiguous)
#define OFF_H   51200    // [32][64]   H e-major, quad-XOR swizzled rows
#define OFF_BAS 53248    // [32][18]   basis per edge
#define OFF_FG  53824    // [32][48]   gathered f[src]
#define OFF_UNI 55360    // union: EF [32][34] (1088) / conv [32][72] (2304)
#define OFF_SRC 57664    // [32] int
#define OFF_DST 57696    // [32] int
#define SMEM_FLOATS 57728
#define SMEM_BYTES (SMEM_FLOATS * 4)   // 230912 B

#define NTHR 256

__global__ __launch_bounds__(NTHR, 1)
void passA(const int* __restrict__ src, const int* __restrict__ dst,
           const float* __restrict__ basis, const float* __restrict__ efeat,
           const float* __restrict__ f, const float* __restrict__ W1,
           const float* __restrict__ b1, const float* __restrict__ W2,
           const float* __restrict__ b2, int E)
{
    extern __shared__ float sm[];
    float* W2s = sm + OFF_W2S;
    float* W1s = sm + OFF_W1S;
    float* Hs  = sm + OFF_H;
    float* bas = sm + OFF_BAS;
    float* fg  = sm + OFF_FG;
    float* uni = sm + OFF_UNI;
    int* srcs  = (int*)(sm + OFF_SRC);
    int* dsts  = (int*)(sm + OFF_DST);

    const int t = threadIdx.x;

    // ---- one-time per block: stage W2 (quad-swizzled, k-contiguous) and W1 ----
    for (int idx = t; idx < 768 * 64; idx += NTHR) {
        int o = idx >> 6, k = idx & 63;
        int q = k >> 2, key = (o >> 2) & 7;
        W2s[(o << 6) | ((q ^ key) << 2) | (k & 3)] = W2[idx];
    }
    for (int idx = t; idx < 64 * 32; idx += NTHR)
        W1s[idx] = W1[idx];
    __syncthreads();

    // GEMM thread mapping: 4 c-pair groups x (8 e-groups x 8 m-groups)
    const int cq = t >> 6;          // 0..3 (c-pair group)
    const int ty = (t >> 3) & 7;    // 0..7
    const int tx = t & 7;           // 0..7
    const int e0 = ty * 4;
    const int m0 = tx * 4;
    const int keyA = ty;            // (e0>>2)&7
    const int keyB = tx;            // (m0>>2)&7

    const int ntiles = (E + 31) >> 5;
    for (int tile = blockIdx.x; tile < ntiles; tile += gridDim.x) {
        const int eg0 = tile << 5;

        // ---- stage 1: edge indices ----
        if (t < 32) {
            int ee = min(eg0 + t, E - 1);
            srcs[t] = src[ee];
            dsts[t] = dst[ee];
        }
        __syncthreads();

        // ---- stage 2: edge feats (union region, [32][34] pad), basis, gathered f ----
        for (int idx = t; idx < 1024; idx += NTHR) {
            int e = idx >> 5, i = idx & 31;
            int ee = min(eg0 + e, E - 1);
            uni[e * 34 + i] = efeat[ee * 32 + i];
        }
        for (int idx = t; idx < 576; idx += NTHR) {      // basis [32][18]
            int e = idx / 18, k = idx - e * 18;
            int ee = min(eg0 + e, E - 1);
            bas[e * 18 + k] = basis[ee * 18 + k];
        }
        for (int idx = t; idx < 1536; idx += NTHR) {     // f gather [32][48]
            int e = idx / 48, r = idx - e * 48;
            fg[idx] = f[srcs[e] * 48 + r];
        }
        __syncthreads();

        // ---- stage 3a: tmp[e][m][d] into registers (48/thread) ----
        float tmpreg[4][4][3];
        #pragma unroll
        for (int ie = 0; ie < 4; ie++) {
            int e = e0 + ie;
            #pragma unroll
            for (int im = 0; im < 4; im++) {
                int m = m0 + im;
                int m1 = m >> 1, rep = m & 1;
                #pragma unroll
                for (int d = 0; d < 3; d++) {
                    float s = 0.f;
                    #pragma unroll
                    for (int d1 = 0; d1 < 3; d1++)
                        s += fg[e * 48 + m1 * 3 + d1] * bas[e * 18 + d1 * 6 + rep * 3 + d];
                    tmpreg[ie][im][d] = s;
                }
            }
        }

        // ---- stage 3b: H = relu(EF @ W1^T + b1), packed f32x2 over k-pairs ----
        {
            int e = t & 31;
            int jg = t >> 5;          // warp id; W1 rows broadcast within warp
            unsigned long long ef[16];
            #pragma unroll
            for (int p = 0; p < 16; p++)
                ef[p] = *reinterpret_cast<const unsigned long long*>(uni + e * 34 + p * 2);
            int ekey = (e >> 2) & 7;
            #pragma unroll
            for (int jj = 0; jj < 8; jj++) {
                int j = jg * 8 + jj;
                const float* wrow = W1s + j * 32;
                unsigned long long acc = 0ull;
                #pragma unroll
                for (int p = 0; p < 16; p++) {
                    unsigned long long w =
                        *reinterpret_cast<const unsigned long long*>(wrow + p * 2);
                    FMA_F32X2(acc, ef[p], w);
                }
                float lo = __uint_as_float((unsigned)acc);
                float hi = __uint_as_float((unsigned)(acc >> 32));
                float a = lo + hi + __ldg(&b1[j]);
                Hs[(e << 6) | ((((j >> 2) ^ ekey) << 2) | (j & 3))] = fmaxf(a, 0.f);
            }
        }
        __syncthreads();   // Hs ready; EF (union) now dead -> conv may overwrite

        // ---- stage 4: RW GEMM, 2 c-channels per pass (A-frag reuse) + conv fuse ----
        float* conv = uni;   // [32][72]
        #pragma unroll 1
        for (int pass = 0; pass < 3; pass++) {
            const int c0 = pass * 8 + cq * 2;      // this thread's c-pair: c0, c0+1
            unsigned long long acc2[2][4][4];      // [ci][ie][im]
            #pragma unroll
            for (int ci = 0; ci < 2; ci++)
                #pragma unroll
                for (int ie = 0; ie < 4; ie++)
                    #pragma unroll
                    for (int im = 0; im < 4; im++)
                        acc2[ci][ie][im] = 0ull;

            const float* Wb0 = W2s + (c0 * 32 + m0) * 64;
            const float* Wb1 = Wb0 + 32 * 64;
            #pragma unroll
            for (int q = 0; q < 16; q++) {
                const int qa = (q ^ keyA) << 2;
                const int qb = (q ^ keyB) << 2;
                ulonglong2 a[4];
                #pragma unroll
                for (int ie = 0; ie < 4; ie++)
                    a[ie] = *reinterpret_cast<const ulonglong2*>(Hs + ((e0 + ie) << 6) + qa);
                ulonglong2 b0[4], b1r[4];
                #pragma unroll
                for (int im = 0; im < 4; im++) {
                    b0[im]  = *reinterpret_cast<const ulonglong2*>(Wb0 + (im << 6) + qb);
                    b1r[im] = *reinterpret_cast<const ulonglong2*>(Wb1 + (im << 6) + qb);
                }
                #pragma unroll
                for (int ie = 0; ie < 4; ie++)
                    #pragma unroll
                    for (int im = 0; im < 4; im++) {
                        FMA_F32X2(acc2[0][ie][im], a[ie].x, b0[im].x);
                        FMA_F32X2(acc2[0][ie][im], a[ie].y, b0[im].y);
                        FMA_F32X2(acc2[1][ie][im], a[ie].x, b1r[im].x);
                        FMA_F32X2(acc2[1][ie][im], a[ie].y, b1r[im].y);
                    }
            }

            // epilogue per c: rw = lo+hi+bias; fuse conv partial; warp-reduce over m
            #pragma unroll
            for (int ci = 0; ci < 2; ci++) {
                const int c = c0 + ci;
                float bvals[4];
                #pragma unroll
                for (int im = 0; im < 4; im++)
                    bvals[im] = __ldg(&b2[c * 32 + m0 + im]);

                float pc[4][3];
                #pragma unroll
                for (int ie = 0; ie < 4; ie++) { pc[ie][0] = 0.f; pc[ie][1] = 0.f; pc[ie][2] = 0.f; }
                #pragma unroll
                for (int ie = 0; ie < 4; ie++)
                    #pragma unroll
                    for (int im = 0; im < 4; im++) {
                        unsigned long long v = acc2[ci][ie][im];
                        float r = __uint_as_float((unsigned)v)
                                + __uint_as_float((unsigned)(v >> 32)) + bvals[im];
                        pc[ie][0] += r * tmpreg[ie][im][0];
                        pc[ie][1] += r * tmpreg[ie][im][1];
                        pc[ie][2] += r * tmpreg[ie][im][2];
                    }
                // reduce over the 8 m-groups (tx = lane bits 0..2) within one warp
                #pragma unroll
                for (int off = 1; off < 8; off <<= 1)
                    #pragma unroll
                    for (int ie = 0; ie < 4; ie++)
                        #pragma unroll
                        for (int d = 0; d < 3; d++)
                            pc[ie][d] += __shfl_xor_sync(0xffffffffu, pc[ie][d], off);
                if (tx == 0) {
                    #pragma unroll
                    for (int ie = 0; ie < 4; ie++)
                        #pragma unroll
                        for (int d = 0; d < 3; d++)
                            conv[(e0 + ie) * 72 + c * 3 + d] = pc[ie][d];
                }
            }
        }
        __syncthreads();

        // ---- stage 5: attention scores, exp, denom atomics, stash v ----
        {
            int e = t >> 3, s = t & 7;   // 32 edges x 8 threads
            int ge = eg0 + e;
            if (ge < E) {
                if (s < 4) {   // s = head
                    float sc = 0.f;
                    #pragma unroll
                    for (int hd = 0; hd < 6; hd++)
                        sc += conv[e * 72 + s * 6 + hd] * conv[e * 72 + 24 + s * 6 + hd];
                    sc *= 0.20412414523193154f;           // 24^-0.5
                    sc = (sc >= 0.f) ? sc : 0.2f * sc;    // leaky_relu(0.2)
                    float ex = expf(sc);                  // shift-invariant softmax (scores ~O(1))
                    g_ex[ge * 4 + s] = ex;
                    atomicAdd(&g_denom[dsts[e] * 4 + s], ex);
                }
                #pragma unroll
                for (int jj = 0; jj < 3; jj++)
                    g_v[ge * 24 + s * 3 + jj] = conv[e * 72 + 48 + s * 3 + jj];
            }
        }
        __syncthreads();
    }
}

__global__ void initK(float* __restrict__ out, int N)
{
    int i = blockIdx.x * blockDim.x + threadIdx.x;
    if (i < N * 24) out[i] = 0.f;
    if (i < N * 4)  g_denom[i] = 0.f;
}

__global__ __launch_bounds__(256)
void passB(const int* __restrict__ dst, float* __restrict__ out, int E)
{
    int idx = blockIdx.x * blockDim.x + threadIdx.x;
    int e = idx >> 3, s = idx & 7;      // 8 threads/edge, 3 outputs each
    if (e >= E) return;
    int d = dst[e];
    int head = s >> 1;                   // 6 floats/head, 3 per thread
    float w = g_ex[e * 4 + head] / g_denom[d * 4 + head];
    #pragma unroll
    for (int jj = 0; jj < 3; jj++) {
        int j = s * 3 + jj;
        atomicAdd(&out[d * 24 + j], w * g_v[e * 24 + j]);
    }
}

extern "C" void kernel_launch(void* const* d_in, const int* in_sizes, int n_in,
                              void* d_out, int out_size)
{
    const int*   src   = (const int*)d_in[0];
    const int*   dst   = (const int*)d_in[1];
    const float* basis = (const float*)d_in[2];
    const float* efeat = (const float*)d_in[3];
    const float* f     = (const float*)d_in[4];
    const float* W1    = (const float*)d_in[5];
    const float* b1    = (const float*)d_in[6];
    const float* W2    = (const float*)d_in[7];
    const float* b2    = (const float*)d_in[8];
    float* out = (float*)d_out;

    int E = in_sizes[0];          // 160000
    int N = in_sizes[4] / 48;     // f is (N,16,3) -> 10000

    cudaFuncSetAttribute(passA, cudaFuncAttributeMaxDynamicSharedMemorySize, SMEM_BYTES);

    initK<<<(N * 24 + 255) / 256, 256>>>(out, N);

    int ntiles = (E + 31) / 32;
    int grid = ntiles < 148 ? ntiles : 148;
    passA<<<grid, NTHR, SMEM_BYTES>>>(src, dst, basis, efeat, f, W1, b1, W2, b2, E);

    passB<<<(E * 8 + 255) / 256, 256>>>(dst, out, E);
}

// round 10
// speedup vs baseline: 1.0001x; 1.0001x over previous
#include <cuda_runtime.h>

// Problem constants (fixed per metadata)
#define EMAX 160000
#define NMAX 10000

// Scratch (device globals — allocation-free)
__device__ float g_ex[EMAX * 4];      // exp(score) per edge/head
__device__ float g_v[EMAX * 24];      // v per edge (m2*d2 = 24)
__device__ float g_denom[NMAX * 4];   // softmax denominator per node/head

// Packed fp32x2 FMA (Blackwell): d.lo += a.lo*b.lo ; d.hi += a.hi*b.hi
#define FMA_F32X2(d, a, b) \
    asm("fma.rn.f32x2 %0, %1, %2, %0;" : "+l"(d) : "l"(a), "l"(b))

// Shared memory layout (in floats)
#define OFF_W2S 0        // [768][64]  W2 original layout, quad-XOR swizzled rows
#define OFF_W1S 49152    // [64][32]   W1 original layout (k contiguous)
#define OFF_H   51200    // [32][64]   H e-major, quad-XOR swizzled rows
#define OFF_BAS 53248    // [32][18]   basis per edge
#define OFF_FG  53824    // [32][48]   gathered f[src]
#define OFF_UNI 55360    // union: EF [32][34] (1088) / conv [32][72] (2304)
#define OFF_SRC 57664    // [32] int
#define OFF_DST 57696    // [32] int
#define SMEM_FLOATS 57728
#define SMEM_BYTES (SMEM_FLOATS * 4)   // 230912 B

#define NTHR 256

__global__ __launch_bounds__(NTHR, 1)
void passA(const int* __restrict__ src, const int* __restrict__ dst,
           const float* __restrict__ basis, const float* __restrict__ efeat,
           const float* __restrict__ f, const float* __restrict__ W1,
           const float* __restrict__ b1, const float* __restrict__ W2,
           const float* __restrict__ b2, int E)
{
    extern __shared__ float sm[];
    float* W2s = sm + OFF_W2S;
    float* W1s = sm + OFF_W1S;
    float* Hs  = sm + OFF_H;
    float* bas = sm + OFF_BAS;
    float* fg  = sm + OFF_FG;
    float* uni = sm + OFF_UNI;
    int* srcs  = (int*)(sm + OFF_SRC);
    int* dsts  = (int*)(sm + OFF_DST);

    const int t = threadIdx.x;

    // ---- one-time per block: stage W2 (quad-swizzled, k-contiguous) and W1 ----
    for (int idx = t; idx < 768 * 64; idx += NTHR) {
        int o = idx >> 6, k = idx & 63;
        int q = k >> 2, key = (o >> 2) & 7;
        W2s[(o << 6) | ((q ^ key) << 2) | (k & 3)] = W2[idx];
    }
    for (int idx = t; idx < 64 * 32; idx += NTHR)
        W1s[idx] = W1[idx];
    __syncthreads();

    // GEMM thread mapping: 4 c-pair groups x (8 e-groups x 8 m-groups)
    const int cq = t >> 6;          // 0..3 (c-pair group)
    const int ty = (t >> 3) & 7;    // 0..7
    const int tx = t & 7;           // 0..7
    const int e0 = ty * 4;
    const int m0 = tx * 4;
    const int keyA = ty;            // (e0>>2)&7
    const int keyB = tx;            // (m0>>2)&7

    const int ntiles = (E + 31) >> 5;
    for (int tile = blockIdx.x; tile < ntiles; tile += gridDim.x) {
        const int eg0 = tile << 5;

        // ---- stage 1: edge indices ----
        if (t < 32) {
            int ee = min(eg0 + t, E - 1);
            srcs[t] = src[ee];
            dsts[t] = dst[ee];
        }
        __syncthreads();

        // ---- stage 2: edge feats (union region, [32][34] pad), basis, gathered f ----
        for (int idx = t; idx < 1024; idx += NTHR) {
            int e = idx >> 5, i = idx & 31;
            int ee = min(eg0 + e, E - 1);
            uni[e * 34 + i] = efeat[ee * 32 + i];
        }
        for (int idx = t; idx < 576; idx += NTHR) {      // basis [32][18]
            int e = idx / 18, k = idx - e * 18;
            int ee = min(eg0 + e, E - 1);
            bas[e * 18 + k] = basis[ee * 18 + k];
        }
        for (int idx = t; idx < 1536; idx += NTHR) {     // f gather [32][48]
            int e = idx / 48, r = idx - e * 48;
            fg[idx] = f[srcs[e] * 48 + r];
        }
        __syncthreads();

        // ---- stage 3a: tmp[e][m][d] into registers (48/thread) ----
        float tmpreg[4][4][3];
        #pragma unroll
        for (int ie = 0; ie < 4; ie++) {
            int e = e0 + ie;
            #pragma unroll
            for (int im = 0; im < 4; im++) {
                int m = m0 + im;
                int m1 = m >> 1, rep = m & 1;
                #pragma unroll
                for (int d = 0; d < 3; d++) {
                    float s = 0.f;
                    #pragma unroll
                    for (int d1 = 0; d1 < 3; d1++)
                        s += fg[e * 48 + m1 * 3 + d1] * bas[e * 18 + d1 * 6 + rep * 3 + d];
                    tmpreg[ie][im][d] = s;
                }
            }
        }

        // ---- stage 3b: H = relu(EF @ W1^T + b1), packed f32x2 over k-pairs ----
        {
            int e = t & 31;
            int jg = t >> 5;          // warp id; W1 rows broadcast within warp
            unsigned long long ef[16];
            #pragma unroll
            for (int p = 0; p < 16; p++)
                ef[p] = *reinterpret_cast<const unsigned long long*>(uni + e * 34 + p * 2);
            int ekey = (e >> 2) & 7;
            #pragma unroll
            for (int jj = 0; jj < 8; jj++) {
                int j = jg * 8 + jj;
                const float* wrow = W1s + j * 32;
                unsigned long long acc = 0ull;
                #pragma unroll
                for (int p = 0; p < 16; p++) {
                    unsigned long long w =
                        *reinterpret_cast<const unsigned long long*>(wrow + p * 2);
                    FMA_F32X2(acc, ef[p], w);
                }
                float lo = __uint_as_float((unsigned)acc);
                float hi = __uint_as_float((unsigned)(acc >> 32));
                float a = lo + hi + __ldg(&b1[j]);
                Hs[(e << 6) | ((((j >> 2) ^ ekey) << 2) | (j & 3))] = fmaxf(a, 0.f);
            }
        }
        __syncthreads();   // Hs ready; EF (union) now dead -> conv may overwrite

        // ---- stage 4: RW GEMM, 2 c-channels per pass (A-frag reuse) + conv fuse ----
        float* conv = uni;   // [32][72]
        #pragma unroll 1
        for (int pass = 0; pass < 3; pass++) {
            const int c0 = pass * 8 + cq * 2;      // this thread's c-pair: c0, c0+1
            unsigned long long acc2[2][4][4];      // [ci][ie][im]
            #pragma unroll
            for (int ci = 0; ci < 2; ci++)
                #pragma unroll
                for (int ie = 0; ie < 4; ie++)
                    #pragma unroll
                    for (int im = 0; im < 4; im++)
                        acc2[ci][ie][im] = 0ull;

            const float* Wb0 = W2s + (c0 * 32 + m0) * 64;
            const float* Wb1 = Wb0 + 32 * 64;
            #pragma unroll
            for (int q = 0; q < 16; q++) {
                const int qa = (q ^ keyA) << 2;
                const int qb = (q ^ keyB) << 2;
                ulonglong2 a[4];
                #pragma unroll
                for (int ie = 0; ie < 4; ie++)
                    a[ie] = *reinterpret_cast<const ulonglong2*>(Hs + ((e0 + ie) << 6) + qa);
                ulonglong2 b0[4], b1r[4];
                #pragma unroll
                for (int im = 0; im < 4; im++) {
                    b0[im]  = *reinterpret_cast<const ulonglong2*>(Wb0 + (im << 6) + qb);
                    b1r[im] = *reinterpret_cast<const ulonglong2*>(Wb1 + (im << 6) + qb);
                }
                #pragma unroll
                for (int ie = 0; ie < 4; ie++)
                    #pragma unroll
                    for (int im = 0; im < 4; im++) {
                        FMA_F32X2(acc2[0][ie][im], a[ie].x, b0[im].x);
                        FMA_F32X2(acc2[0][ie][im], a[ie].y, b0[im].y);
                        FMA_F32X2(acc2[1][ie][im], a[ie].x, b1r[im].x);
                        FMA_F32X2(acc2[1][ie][im], a[ie].y, b1r[im].y);
                    }
            }

            // epilogue per c: rw = lo+hi+bias; fuse conv partial; warp-reduce over m
            #pragma unroll
            for (int ci = 0; ci < 2; ci++) {
                const int c = c0 + ci;
                float bvals[4];
                #pragma unroll
                for (int im = 0; im < 4; im++)
                    bvals[im] = __ldg(&b2[c * 32 + m0 + im]);

                float pc[4][3];
                #pragma unroll
                for (int ie = 0; ie < 4; ie++) { pc[ie][0] = 0.f; pc[ie][1] = 0.f; pc[ie][2] = 0.f; }
                #pragma unroll
                for (int ie = 0; ie < 4; ie++)
                    #pragma unroll
                    for (int im = 0; im < 4; im++) {
                        unsigned long long v = acc2[ci][ie][im];
                        float r = __uint_as_float((unsigned)v)
                                + __uint_as_float((unsigned)(v >> 32)) + bvals[im];
                        pc[ie][0] += r * tmpreg[ie][im][0];
                        pc[ie][1] += r * tmpreg[ie][im][1];
                        pc[ie][2] += r * tmpreg[ie][im][2];
                    }
                // reduce over the 8 m-groups (tx = lane bits 0..2) within one warp
                #pragma unroll
                for (int off = 1; off < 8; off <<= 1)
                    #pragma unroll
                    for (int ie = 0; ie < 4; ie++)
                        #pragma unroll
                        for (int d = 0; d < 3; d++)
                            pc[ie][d] += __shfl_xor_sync(0xffffffffu, pc[ie][d], off);
                if (tx == 0) {
                    #pragma unroll
                    for (int ie = 0; ie < 4; ie++)
                        #pragma unroll
                        for (int d = 0; d < 3; d++)
                            conv[(e0 + ie) * 72 + c * 3 + d] = pc[ie][d];
                }
            }
        }
        __syncthreads();

        // ---- stage 5: attention scores, exp, denom atomics, stash v ----
        {
            int e = t >> 3, s = t & 7;   // 32 edges x 8 threads
            int ge = eg0 + e;
            if (ge < E) {
                if (s < 4) {   // s = head
                    float sc = 0.f;
                    #pragma unroll
                    for (int hd = 0; hd < 6; hd++)
                        sc += conv[e * 72 + s * 6 + hd] * conv[e * 72 + 24 + s * 6 + hd];
                    sc *= 0.20412414523193154f;           // 24^-0.5
                    sc = (sc >= 0.f) ? sc : 0.2f * sc;    // leaky_relu(0.2)
                    float ex = expf(sc);                  // shift-invariant softmax (scores ~O(1))
                    g_ex[ge * 4 + s] = ex;
                    atomicAdd(&g_denom[dsts[e] * 4 + s], ex);
                }
                #pragma unroll
                for (int jj = 0; jj < 3; jj++)
                    g_v[ge * 24 + s * 3 + jj] = conv[e * 72 + 48 + s * 3 + jj];
            }
        }
        __syncthreads();
    }
}

__global__ void initK(float* __restrict__ out, int N)
{
    int i = blockIdx.x * blockDim.x + threadIdx.x;
    if (i < N * 24) out[i] = 0.f;
    if (i < N * 4)  g_denom[i] = 0.f;
}

__global__ __launch_bounds__(256)
void passB(const int* __restrict__ dst, float* __restrict__ out, int E)
{
    int idx = blockIdx.x * blockDim.x + threadIdx.x;
    int e = idx >> 3, s = idx & 7;      // 8 threads/edge, 3 outputs each
    if (e >= E) return;
    int d = dst[e];
    int head = s >> 1;                   // 6 floats/head, 3 per thread
    float w = g_ex[e * 4 + head] / g_denom[d * 4 + head];
    #pragma unroll
    for (int jj = 0; jj < 3; jj++) {
        int j = s * 3 + jj;
        atomicAdd(&out[d * 24 + j], w * g_v[e * 24 + j]);
    }
}

extern "C" void kernel_launch(void* const* d_in, const int* in_sizes, int n_in,
                              void* d_out, int out_size)
{
    const int*   src   = (const int*)d_in[0];
    const int*   dst   = (const int*)d_in[1];
    const float* basis = (const float*)d_in[2];
    const float* efeat = (const float*)d_in[3];
    const float* f     = (const float*)d_in[4];
    const float* W1    = (const float*)d_in[5];
    const float* b1    = (const float*)d_in[6];
    const float* W2    = (const float*)d_in[7];
    const float* b2    = (const float*)d_in[8];
    float* out = (float*)d_out;

    int E = in_sizes[0];          // 160000
    int N = in_sizes[4] / 48;     // f is (N,16,3) -> 10000

    cudaFuncSetAttribute(passA, cudaFuncAttributeMaxDynamicSharedMemorySize, SMEM_BYTES);

    initK<<<(N * 24 + 255) / 256, 256>>>(out, N);

    int ntiles = (E + 31) / 32;
    int grid = ntiles < 148 ? ntiles : 148;
    passA<<<grid, NTHR, SMEM_BYTES>>>(src, dst, basis, efeat, f, W1, b1, W2, b2, E);

    passB<<<(E * 8 + 255) / 256, 256>>>(dst, out, E);
}

// round 11
// speedup vs baseline: 1.0010x; 1.0009x over previous
#include <cuda_runtime.h>

// Problem constants (fixed per metadata)
#define EMAX 160000
#define NMAX 10000

// Scratch (device globals — allocation-free)
__device__ float g_ex[EMAX * 4];      // exp(score) per edge/head
__device__ float g_v[EMAX * 24];      // v per edge (m2*d2 = 24)
__device__ float g_denom[NMAX * 4];   // softmax denominator per node/head

// Packed fp32x2 FMA (Blackwell): d.lo += a.lo*b.lo ; d.hi += a.hi*b.hi
#define FMA_F32X2(d, a, b) \
    asm("fma.rn.f32x2 %0, %1, %2, %0;" : "+l"(d) : "l"(a), "l"(b))

// Shared memory layout (in floats)
#define OFF_W2S 0        // [768][64]  W2 original layout, quad-XOR swizzled rows
#define OFF_W1S 49152    // [64][32]   W1 original layout (k contiguous)
#define OFF_H   51200    // [32][64]   H e-major, quad-XOR swizzled rows
#define OFF_BAS 53248    // [32][18]   basis per edge
#define OFF_FG  53824    // [32][48]   gathered f[src]
#define OFF_UNI 55360    // union: EF [32][34] (1088) / conv [32][72] (2304)
#define OFF_SRC 57664    // [32] int
#define OFF_DST 57696    // [32] int
#define SMEM_FLOATS 57728
#define SMEM_BYTES (SMEM_FLOATS * 4)   // 230912 B

#define NTHR 256

__global__ __launch_bounds__(NTHR, 1)
void passA(const int* __restrict__ src, const int* __restrict__ dst,
           const float* __restrict__ basis, const float* __restrict__ efeat,
           const float* __restrict__ f, const float* __restrict__ W1,
           const float* __restrict__ b1, const float* __restrict__ W2,
           const float* __restrict__ b2, int E)
{
    extern __shared__ float sm[];
    float* W2s = sm + OFF_W2S;
    float* W1s = sm + OFF_W1S;
    float* Hs  = sm + OFF_H;
    float* bas = sm + OFF_BAS;
    float* fg  = sm + OFF_FG;
    float* uni = sm + OFF_UNI;
    int* srcs  = (int*)(sm + OFF_SRC);
    int* dsts  = (int*)(sm + OFF_DST);

    const int t = threadIdx.x;

    // ---- one-time per block: stage W2 (quad-swizzled, k-contiguous) and W1 ----
    for (int idx = t; idx < 768 * 64; idx += NTHR) {
        int o = idx >> 6, k = idx & 63;
        int q = k >> 2, key = (o >> 2) & 7;
        W2s[(o << 6) | ((q ^ key) << 2) | (k & 3)] = W2[idx];
    }
    for (int idx = t; idx < 64 * 32; idx += NTHR)
        W1s[idx] = W1[idx];
    __syncthreads();

    // GEMM thread mapping: 4 c-pair groups x (8 e-groups x 8 m-groups)
    const int cq = t >> 6;          // 0..3 (c-pair group)
    const int ty = (t >> 3) & 7;    // 0..7
    const int tx = t & 7;           // 0..7
    const int e0 = ty * 4;
    const int m0 = tx * 4;
    const int keyA = ty;            // (e0>>2)&7
    const int keyB = tx;            // (m0>>2)&7

    const int ntiles = (E + 31) >> 5;
    for (int tile = blockIdx.x; tile < ntiles; tile += gridDim.x) {
        const int eg0 = tile << 5;

        // ---- stage 1: edge indices ----
        if (t < 32) {
            int ee = min(eg0 + t, E - 1);
            srcs[t] = src[ee];
            dsts[t] = dst[ee];
        }
        __syncthreads();

        // ---- stage 2: edge feats (union region, [32][34] pad), basis, gathered f ----
        for (int idx = t; idx < 1024; idx += NTHR) {
            int e = idx >> 5, i = idx & 31;
            int ee = min(eg0 + e, E - 1);
            uni[e * 34 + i] = efeat[ee * 32 + i];
        }
        for (int idx = t; idx < 576; idx += NTHR) {      // basis [32][18]
            int e = idx / 18, k = idx - e * 18;
            int ee = min(eg0 + e, E - 1);
            bas[e * 18 + k] = basis[ee * 18 + k];
        }
        for (int idx = t; idx < 1536; idx += NTHR) {     // f gather [32][48]
            int e = idx / 48, r = idx - e * 48;
            fg[idx] = f[srcs[e] * 48 + r];
        }
        __syncthreads();

        // ---- stage 3a: tmp[e][m][d] into registers (48/thread) ----
        float tmpreg[4][4][3];
        #pragma unroll
        for (int ie = 0; ie < 4; ie++) {
            int e = e0 + ie;
            #pragma unroll
            for (int im = 0; im < 4; im++) {
                int m = m0 + im;
                int m1 = m >> 1, rep = m & 1;
                #pragma unroll
                for (int d = 0; d < 3; d++) {
                    float s = 0.f;
                    #pragma unroll
                    for (int d1 = 0; d1 < 3; d1++)
                        s += fg[e * 48 + m1 * 3 + d1] * bas[e * 18 + d1 * 6 + rep * 3 + d];
                    tmpreg[ie][im][d] = s;
                }
            }
        }

        // ---- stage 3b: H = relu(EF @ W1^T + b1), packed f32x2 over k-pairs ----
        {
            int e = t & 31;
            int jg = t >> 5;          // warp id; W1 rows broadcast within warp
            unsigned long long ef[16];
            #pragma unroll
            for (int p = 0; p < 16; p++)
                ef[p] = *reinterpret_cast<const unsigned long long*>(uni + e * 34 + p * 2);
            int ekey = (e >> 2) & 7;
            #pragma unroll
            for (int jj = 0; jj < 8; jj++) {
                int j = jg * 8 + jj;
                const float* wrow = W1s + j * 32;
                unsigned long long acc = 0ull;
                #pragma unroll
                for (int p = 0; p < 16; p++) {
                    unsigned long long w =
                        *reinterpret_cast<const unsigned long long*>(wrow + p * 2);
                    FMA_F32X2(acc, ef[p], w);
                }
                float lo = __uint_as_float((unsigned)acc);
                float hi = __uint_as_float((unsigned)(acc >> 32));
                float a = lo + hi + __ldg(&b1[j]);
                Hs[(e << 6) | ((((j >> 2) ^ ekey) << 2) | (j & 3))] = fmaxf(a, 0.f);
            }
        }
        __syncthreads();   // Hs ready; EF (union) now dead -> conv may overwrite

        // ---- stage 4: RW GEMM, 2 c-channels per pass (A-frag reuse) + conv fuse ----
        float* conv = uni;   // [32][72]
        #pragma unroll 1
        for (int pass = 0; pass < 3; pass++) {
            const int c0 = pass * 8 + cq * 2;      // this thread's c-pair: c0, c0+1
            unsigned long long acc2[2][4][4];      // [ci][ie][im]
            #pragma unroll
            for (int ci = 0; ci < 2; ci++)
                #pragma unroll
                for (int ie = 0; ie < 4; ie++)
                    #pragma unroll
                    for (int im = 0; im < 4; im++)
                        acc2[ci][ie][im] = 0ull;

            const float* Wb0 = W2s + (c0 * 32 + m0) * 64;
            const float* Wb1 = Wb0 + 32 * 64;
            #pragma unroll
            for (int q = 0; q < 16; q++) {
                const int qa = (q ^ keyA) << 2;
                const int qb = (q ^ keyB) << 2;
                ulonglong2 a[4];
                #pragma unroll
                for (int ie = 0; ie < 4; ie++)
                    a[ie] = *reinterpret_cast<const ulonglong2*>(Hs + ((e0 + ie) << 6) + qa);
                ulonglong2 b0[4], b1r[4];
                #pragma unroll
                for (int im = 0; im < 4; im++) {
                    b0[im]  = *reinterpret_cast<const ulonglong2*>(Wb0 + (im << 6) + qb);
                    b1r[im] = *reinterpret_cast<const ulonglong2*>(Wb1 + (im << 6) + qb);
                }
                #pragma unroll
                for (int ie = 0; ie < 4; ie++)
                    #pragma unroll
                    for (int im = 0; im < 4; im++) {
                        FMA_F32X2(acc2[0][ie][im], a[ie].x, b0[im].x);
                        FMA_F32X2(acc2[0][ie][im], a[ie].y, b0[im].y);
                        FMA_F32X2(acc2[1][ie][im], a[ie].x, b1r[im].x);
                        FMA_F32X2(acc2[1][ie][im], a[ie].y, b1r[im].y);
                    }
            }

            // epilogue per c: rw = lo+hi+bias; fuse conv partial; warp-reduce over m
            #pragma unroll
            for (int ci = 0; ci < 2; ci++) {
                const int c = c0 + ci;
                float bvals[4];
                #pragma unroll
                for (int im = 0; im < 4; im++)
                    bvals[im] = __ldg(&b2[c * 32 + m0 + im]);

                float pc[4][3];
                #pragma unroll
                for (int ie = 0; ie < 4; ie++) { pc[ie][0] = 0.f; pc[ie][1] = 0.f; pc[ie][2] = 0.f; }
                #pragma unroll
                for (int ie = 0; ie < 4; ie++)
                    #pragma unroll
                    for (int im = 0; im < 4; im++) {
                        unsigned long long v = acc2[ci][ie][im];
                        float r = __uint_as_float((unsigned)v)
                                + __uint_as_float((unsigned)(v >> 32)) + bvals[im];
                        pc[ie][0] += r * tmpreg[ie][im][0];
                        pc[ie][1] += r * tmpreg[ie][im][1];
                        pc[ie][2] += r * tmpreg[ie][im][2];
                    }
                // reduce over the 8 m-groups (tx = lane bits 0..2) within one warp
                #pragma unroll
                for (int off = 1; off < 8; off <<= 1)
                    #pragma unroll
                    for (int ie = 0; ie < 4; ie++)
                        #pragma unroll
                        for (int d = 0; d < 3; d++)
                            pc[ie][d] += __shfl_xor_sync(0xffffffffu, pc[ie][d], off);
                if (tx == 0) {
                    #pragma unroll
                    for (int ie = 0; ie < 4; ie++)
                        #pragma unroll
                        for (int d = 0; d < 3; d++)
                            conv[(e0 + ie) * 72 + c * 3 + d] = pc[ie][d];
                }
            }
        }
        __syncthreads();

        // ---- stage 5: attention scores, exp, denom atomics, stash v ----
        {
            int e = t >> 3, s = t & 7;   // 32 edges x 8 threads
            int ge = eg0 + e;
            if (ge < E) {
                if (s < 4) {   // s = head
                    float sc = 0.f;
                    #pragma unroll
                    for (int hd = 0; hd < 6; hd++)
                        sc += conv[e * 72 + s * 6 + hd] * conv[e * 72 + 24 + s * 6 + hd];
                    sc *= 0.20412414523193154f;           // 24^-0.5
                    sc = (sc >= 0.f) ? sc : 0.2f * sc;    // leaky_relu(0.2)
                    float ex = expf(sc);                  // shift-invariant softmax (scores ~O(1))
                    g_ex[ge * 4 + s] = ex;
                    atomicAdd(&g_denom[dsts[e] * 4 + s], ex);
                }
                #pragma unroll
                for (int jj = 0; jj < 3; jj++)
                    g_v[ge * 24 + s * 3 + jj] = conv[e * 72 + 48 + s * 3 + jj];
            }
        }
        __syncthreads();
    }
}

__global__ void initK(float* __restrict__ out, int N)
{
    int i = blockIdx.x * blockDim.x + threadIdx.x;
    if (i < N * 24) out[i] = 0.f;
    if (i < N * 4)  g_denom[i] = 0.f;
}

__global__ __launch_bounds__(256)
void passB(const int* __restrict__ dst, float* __restrict__ out, int E)
{
    int idx = blockIdx.x * blockDim.x + threadIdx.x;
    int e = idx >> 3, s = idx & 7;      // 8 threads/edge, 3 outputs each
    if (e >= E) return;
    int d = dst[e];
    int head = s >> 1;                   // 6 floats/head, 3 per thread
    float w = g_ex[e * 4 + head] / g_denom[d * 4 + head];
    #pragma unroll
    for (int jj = 0; jj < 3; jj++) {
        int j = s * 3 + jj;
        atomicAdd(&out[d * 24 + j], w * g_v[e * 24 + j]);
    }
}

extern "C" void kernel_launch(void* const* d_in, const int* in_sizes, int n_in,
                              void* d_out, int out_size)
{
    const int*   src   = (const int*)d_in[0];
    const int*   dst   = (const int*)d_in[1];
    const float* basis = (const float*)d_in[2];
    const float* efeat = (const float*)d_in[3];
    const float* f     = (const float*)d_in[4];
    const float* W1    = (const float*)d_in[5];
    const float* b1    = (const float*)d_in[6];
    const float* W2    = (const float*)d_in[7];
    const float* b2    = (const float*)d_in[8];
    float* out = (float*)d_out;

    int E = in_sizes[0];          // 160000
    int N = in_sizes[4] / 48;     // f is (N,16,3) -> 10000

    cudaFuncSetAttribute(passA, cudaFuncAttributeMaxDynamicSharedMemorySize, SMEM_BYTES);

    initK<<<(N * 24 + 255) / 256, 256>>>(out, N);

    int ntiles = (E + 31) / 32;
    int grid = ntiles < 148 ? ntiles : 148;
    passA<<<grid, NTHR, SMEM_BYTES>>>(src, dst, basis, efeat, f, W1, b1, W2, b2, E);

    passB<<<(E * 8 + 255) / 256, 256>>>(dst, out, E);
}

// round 12
// speedup vs baseline: 1.7072x; 1.7055x over previous
#include <cuda_runtime.h>
#include <cuda_bf16.h>

// Problem constants (fixed per metadata)
#define EMAX 160000
#define NMAX 10000

// Scratch (device globals — allocation-free)
__device__ float g_ex[EMAX * 4];      // exp(score) per edge/head
__device__ float g_v[EMAX * 24];      // v per edge (m2*d2 = 24)
__device__ float g_denom[NMAX * 4];   // softmax denominator per node/head

// Packed fp32x2 FMA (Blackwell)
#define FMA_F32X2(d, a, b) \
    asm("fma.rn.f32x2 %0, %1, %2, %0;" : "+l"(d) : "l"(a), "l"(b))
#define PACK_F32X2(out, lo, hi) \
    asm("mov.b64 %0, {%1, %2};" : "=l"(out) : "f"(lo), "f"(hi))

// m16n8k16 bf16 MMA, fp32 accumulate (register tensor-core path)
__device__ __forceinline__ void mma_bf16(float d[4], const unsigned a[4],
                                         unsigned b0, unsigned b1) {
    asm volatile(
        "mma.sync.aligned.m16n8k16.row.col.f32.bf16.bf16.f32 "
        "{%0,%1,%2,%3},{%4,%5,%6,%7},{%8,%9},{%0,%1,%2,%3};"
        : "+f"(d[0]), "+f"(d[1]), "+f"(d[2]), "+f"(d[3])
        : "r"(a[0]), "r"(a[1]), "r"(a[2]), "r"(a[3]), "r"(b0), "r"(b1));
}
__device__ __forceinline__ void ldsm_x4(unsigned r[4], unsigned addr) {
    asm volatile("ldmatrix.sync.aligned.m8n8.x4.shared.b16 {%0,%1,%2,%3}, [%4];"
        : "=r"(r[0]), "=r"(r[1]), "=r"(r[2]), "=r"(r[3]) : "r"(addr));
}

// Shared memory layout (byte offsets)
#define SM_W2HI 0        // [768 o][64 k] bf16 hi, 128B rows, 16B-octet XOR swizzle (98304)
#define SM_W2LO 98304    // bf16 lo plane                                           (98304)
#define SM_W1   196608   // [64][32] fp32                                           (8192)
#define SM_HHI  204800   // [32 e][64 k] bf16 hi, 128B rows, octet swizzle          (4096)
#define SM_HLO  208896   // bf16 lo plane                                           (4096)
#define SM_UNI  212992   // union: bas(2304B)+fg(6144B)+EF[32][34](4352B) = 12800B
                         //        then tmp[32][96] f32 (12288B) then conv[32][72]
#define SM_IDX  225792   // src[32], dst[32]                                        (256)
#define SMEM_BYTES 226048

#define NTHR 256

__global__ __launch_bounds__(NTHR, 1)
void passA(const int* __restrict__ src, const int* __restrict__ dst,
           const float* __restrict__ basis, const float* __restrict__ efeat,
           const float* __restrict__ f, const float* __restrict__ W1,
           const float* __restrict__ b1, const float* __restrict__ W2,
           const float* __restrict__ b2, int E)
{
    extern __shared__ char smc[];
    float* W1s  = (float*)(smc + SM_W1);
    float* uniF = (float*)(smc + SM_UNI);
    float* bas  = uniF;            // 576 floats
    float* fg   = uniF + 576;      // 1536 floats
    float* efs  = uniF + 2112;     // [32][34] floats
    float* tmpf = uniF;            // [32][96] after repurpose
    float* conv = uniF;            // [32][72] after second repurpose
    int* srcs   = (int*)(smc + SM_IDX);
    int* dsts   = (int*)(smc + SM_IDX + 128);
    const unsigned sbase = (unsigned)__cvta_generic_to_shared(smc);

    const int t = threadIdx.x;
    const int w = t >> 5, lane = t & 31;
    const int gid = lane >> 2, tig = lane & 3;

    // ldmatrix lane-address constants
    const int sel   = lane >> 3;
    const int arow  = (lane & 7) + ((sel & 1) << 3);  // A: row within 16-block
    const int ahalf = sel >> 1;                        // A: k-octet half
    const int bnb   = lane >> 4;                       // B: which 8-o block of pair
    const int bhalf = (lane >> 3) & 1;                 // B: k-octet half
    const int brow  = lane & 7;                        // B: o row within 8

    // ---- one-time per block: W2 -> bf16 hi/lo (octet-swizzled), W1 fp32 ----
    for (int idx = t; idx < 768 * 64; idx += NTHR) {
        int o = idx >> 6, k = idx & 63;
        float wv = W2[idx];
        __nv_bfloat16 hb = __float2bfloat16(wv);
        __nv_bfloat16 lb = __float2bfloat16(wv - __bfloat162float(hb));
        int off = o * 128 + (((k >> 3) ^ (o & 7)) << 4) + ((k & 7) << 1);
        *(unsigned short*)(smc + SM_W2HI + off) = __bfloat16_as_ushort(hb);
        *(unsigned short*)(smc + SM_W2LO + off) = __bfloat16_as_ushort(lb);
    }
    for (int idx = t; idx < 2048; idx += NTHR) W1s[idx] = W1[idx];
    __syncthreads();

    const int ntiles = (E + 31) >> 5;
    for (int tile = blockIdx.x; tile < ntiles; tile += gridDim.x) {
        const int eg0 = tile << 5;

        // ---- stage 1: edge indices ----
        if (t < 32) {
            int ee = min(eg0 + t, E - 1);
            srcs[t] = src[ee];
            dsts[t] = dst[ee];
        }
        __syncthreads();

        // ---- stage 2: EF, basis, gathered f ----
        for (int idx = t; idx < 1024; idx += NTHR) {
            int e = idx >> 5, i = idx & 31;
            int ee = min(eg0 + e, E - 1);
            efs[e * 34 + i] = efeat[ee * 32 + i];
        }
        for (int idx = t; idx < 576; idx += NTHR) {
            int e = idx / 18, k = idx - e * 18;
            int ee = min(eg0 + e, E - 1);
            bas[e * 18 + k] = basis[ee * 18 + k];
        }
        for (int idx = t; idx < 1536; idx += NTHR) {
            int e = idx / 48, r = idx - e * 48;
            fg[idx] = f[srcs[e] * 48 + r];
        }
        __syncthreads();

        // ---- stage 3a: tmp values into regs (e = t>>3 owns m-group t&7) ----
        float tv[12];
        {
            int e = t >> 3, mg = t & 7;
            #pragma unroll
            for (int mm = 0; mm < 4; mm++) {
                int m = mg * 4 + mm, m1 = m >> 1, rep = m & 1;
                #pragma unroll
                for (int d = 0; d < 3; d++) {
                    float s = 0.f;
                    #pragma unroll
                    for (int d1 = 0; d1 < 3; d1++)
                        s += fg[e * 48 + m1 * 3 + d1] * bas[e * 18 + d1 * 6 + rep * 3 + d];
                    tv[mm * 3 + d] = s;
                }
            }
        }
        // ---- stage 3b: MLP (f32x2) -> bf16 hi/lo packs in regs ----
        unsigned hip[4], lop[4];
        {
            int e = lane, jg = w;
            unsigned long long ef[16];
            #pragma unroll
            for (int p = 0; p < 16; p++)
                ef[p] = *(const unsigned long long*)(efs + e * 34 + p * 2);
            float hv[8];
            #pragma unroll
            for (int jj = 0; jj < 8; jj++) {
                int j = jg * 8 + jj;
                const float* wrow = W1s + j * 32;
                unsigned long long acc = 0ull;
                #pragma unroll
                for (int p = 0; p < 16; p++) {
                    unsigned long long wv = *(const unsigned long long*)(wrow + p * 2);
                    FMA_F32X2(acc, ef[p], wv);
                }
                float h = __uint_as_float((unsigned)acc)
                        + __uint_as_float((unsigned)(acc >> 32)) + __ldg(&b1[j]);
                hv[jj] = fmaxf(h, 0.f);
            }
            #pragma unroll
            for (int q2 = 0; q2 < 4; q2++) {
                __nv_bfloat16 h0 = __float2bfloat16(hv[q2 * 2]);
                __nv_bfloat16 h1 = __float2bfloat16(hv[q2 * 2 + 1]);
                __nv_bfloat16 l0 = __float2bfloat16(hv[q2 * 2]     - __bfloat162float(h0));
                __nv_bfloat16 l1 = __float2bfloat16(hv[q2 * 2 + 1] - __bfloat162float(h1));
                hip[q2] = (unsigned)__bfloat16_as_ushort(h0) | ((unsigned)__bfloat16_as_ushort(h1) << 16);
                lop[q2] = (unsigned)__bfloat16_as_ushort(l0) | ((unsigned)__bfloat16_as_ushort(l1) << 16);
            }
        }
        __syncthreads();   // bas/fg/efs reads done -> union may be overwritten

        // ---- stage 4a: write tmp (pair-swizzled) and H hi/lo planes ----
        {
            int e = t >> 3, mg = t & 7;
            #pragma unroll
            for (int mm = 0; mm < 4; mm++) {
                int m = mg * 4 + mm, mp = m >> 1;
                #pragma unroll
                for (int d = 0; d < 3; d++)
                    tmpf[e * 96 + d * 32 + (((mp ^ (e & 7)) << 1) | (m & 1))] = tv[mm * 3 + d];
            }
        }
        {
            int e = lane, jg = w;
            int off = e * 128 + ((jg ^ (e & 7)) << 4);
            *(uint4*)(smc + SM_HHI + off) = make_uint4(hip[0], hip[1], hip[2], hip[3]);
            *(uint4*)(smc + SM_HLO + off) = make_uint4(lop[0], lop[1], lop[2], lop[3]);
        }
        __syncthreads();

        // ---- stage 4b: HMMA GEMM (3-term bf16 split), warp w owns o=[96w,96w+96) ----
        unsigned ah[2][4][4], al[2][4][4];
        #pragma unroll
        for (int eb = 0; eb < 2; eb++) {
            unsigned rowoff = (unsigned)((eb * 16 + arow) * 128);
            #pragma unroll
            for (int K = 0; K < 4; K++) {
                unsigned oct = (unsigned)(((2 * K + ahalf) ^ (lane & 7)) << 4);
                ldsm_x4(ah[eb][K], sbase + SM_HHI + rowoff + oct);
                ldsm_x4(al[eb][K], sbase + SM_HLO + rowoff + oct);
            }
        }
        float D[2][12][4];
        #pragma unroll
        for (int nb = 0; nb < 12; nb++) {
            float2 bb = __ldg((const float2*)(b2 + w * 96 + nb * 8 + tig * 2));
            #pragma unroll
            for (int eb = 0; eb < 2; eb++) {
                D[eb][nb][0] = bb.x; D[eb][nb][1] = bb.y;
                D[eb][nb][2] = bb.x; D[eb][nb][3] = bb.y;
            }
        }
        {
            unsigned browoff = (unsigned)((w * 96 + bnb * 8 + brow) * 128);
            #pragma unroll
            for (int K = 0; K < 4; K++) {
                unsigned octb = (unsigned)(((2 * K + bhalf) ^ brow) << 4);
                #pragma unroll
                for (int pr = 0; pr < 6; pr++) {
                    unsigned off = browoff + (unsigned)(pr * 2048) + octb;  // 16 rows*128B
                    unsigned bh[4], bl[4];
                    ldsm_x4(bh, sbase + SM_W2HI + off);
                    ldsm_x4(bl, sbase + SM_W2LO + off);
                    #pragma unroll
                    for (int eb = 0; eb < 2; eb++) {
                        mma_bf16(D[eb][2 * pr],     ah[eb][K], bh[0], bh[1]);
                        mma_bf16(D[eb][2 * pr],     al[eb][K], bh[0], bh[1]);
                        mma_bf16(D[eb][2 * pr],     ah[eb][K], bl[0], bl[1]);
                        mma_bf16(D[eb][2 * pr + 1], ah[eb][K], bh[2], bh[3]);
                        mma_bf16(D[eb][2 * pr + 1], al[eb][K], bh[2], bh[3]);
                        mma_bf16(D[eb][2 * pr + 1], ah[eb][K], bl[2], bl[3]);
                    }
                }
            }
        }

        // ---- epilogue: conv[e][c][d] = sum_m rw[e][c][m]*tmp[e][m][d] ----
        float pc[2][2][3][3];   // [eb][h][ci][d]
        #pragma unroll
        for (int eb = 0; eb < 2; eb++)
            #pragma unroll
            for (int h = 0; h < 2; h++) {
                int e_l = eb * 16 + h * 8 + gid;       // e&7 == gid
                unsigned long long tp[3][4];
                #pragma unroll
                for (int d = 0; d < 3; d++)
                    #pragma unroll
                    for (int j = 0; j < 4; j++) {
                        int mp = j * 4 + tig;
                        tp[d][j] = *(const unsigned long long*)
                            (tmpf + e_l * 96 + d * 32 + ((mp ^ gid) << 1));
                    }
                unsigned long long acc[3][3];
                #pragma unroll
                for (int ci = 0; ci < 3; ci++)
                    #pragma unroll
                    for (int d = 0; d < 3; d++)
                        acc[ci][d] = 0ull;
                #pragma unroll
                for (int ci = 0; ci < 3; ci++)
                    #pragma unroll
                    for (int j = 0; j < 4; j++) {
                        unsigned long long pd;
                        PACK_F32X2(pd, D[eb][ci * 4 + j][h * 2], D[eb][ci * 4 + j][h * 2 + 1]);
                        #pragma unroll
                        for (int d = 0; d < 3; d++)
                            FMA_F32X2(acc[ci][d], pd, tp[d][j]);
                    }
                #pragma unroll
                for (int ci = 0; ci < 3; ci++)
                    #pragma unroll
                    for (int d = 0; d < 3; d++)
                        pc[eb][h][ci][d] = __uint_as_float((unsigned)acc[ci][d])
                                         + __uint_as_float((unsigned)(acc[ci][d] >> 32));
            }
        // reduce m-partials across tig (lane bits 0-1)
        #pragma unroll
        for (int off = 1; off < 4; off <<= 1)
            #pragma unroll
            for (int eb = 0; eb < 2; eb++)
                #pragma unroll
                for (int h = 0; h < 2; h++)
                    #pragma unroll
                    for (int ci = 0; ci < 3; ci++)
                        #pragma unroll
                        for (int d = 0; d < 3; d++)
                            pc[eb][h][ci][d] += __shfl_xor_sync(0xffffffffu, pc[eb][h][ci][d], off);
        __syncthreads();   // ALL tmp reads complete before conv overwrites union
        if (tig == 0) {
            #pragma unroll
            for (int eb = 0; eb < 2; eb++)
                #pragma unroll
                for (int h = 0; h < 2; h++) {
                    int e_l = eb * 16 + h * 8 + gid;
                    #pragma unroll
                    for (int ci = 0; ci < 3; ci++) {
                        int c = w * 3 + ci;
                        #pragma unroll
                        for (int d = 0; d < 3; d++)
                            conv[e_l * 72 + c * 3 + d] = pc[eb][h][ci][d];
                    }
                }
        }
        __syncthreads();

        // ---- stage 5: attention scores, exp, denom atomics, stash v ----
        {
            int e = t >> 3, s = t & 7;
            int ge = eg0 + e;
            if (ge < E) {
                if (s < 4) {
                    float sc = 0.f;
                    #pragma unroll
                    for (int hd = 0; hd < 6; hd++)
                        sc += conv[e * 72 + s * 6 + hd] * conv[e * 72 + 24 + s * 6 + hd];
                    sc *= 0.20412414523193154f;           // 24^-0.5
                    sc = (sc >= 0.f) ? sc : 0.2f * sc;    // leaky_relu(0.2)
                    float ex = expf(sc);                  // shift-invariant softmax
                    g_ex[ge * 4 + s] = ex;
                    atomicAdd(&g_denom[dsts[e] * 4 + s], ex);
                }
                #pragma unroll
                for (int jj = 0; jj < 3; jj++)
                    g_v[ge * 24 + s * 3 + jj] = conv[e * 72 + 48 + s * 3 + jj];
            }
        }
        __syncthreads();
    }
}

__global__ void initK(float* __restrict__ out, int N)
{
    int i = blockIdx.x * blockDim.x + threadIdx.x;
    if (i < N * 24) out[i] = 0.f;
    if (i < N * 4)  g_denom[i] = 0.f;
}

__global__ __launch_bounds__(256)
void passB(const int* __restrict__ dst, float* __restrict__ out, int E)
{
    int idx = blockIdx.x * blockDim.x + threadIdx.x;
    int e = idx >> 3, s = idx & 7;      // 8 threads/edge, 3 outputs each
    if (e >= E) return;
    int d = dst[e];
    int head = s >> 1;                   // 6 floats/head, 3 per thread
    float wgt = g_ex[e * 4 + head] / g_denom[d * 4 + head];
    #pragma unroll
    for (int jj = 0; jj < 3; jj++) {
        int j = s * 3 + jj;
        atomicAdd(&out[d * 24 + j], wgt * g_v[e * 24 + j]);
    }
}

extern "C" void kernel_launch(void* const* d_in, const int* in_sizes, int n_in,
                              void* d_out, int out_size)
{
    const int*   src   = (const int*)d_in[0];
    const int*   dst   = (const int*)d_in[1];
    const float* basis = (const float*)d_in[2];
    const float* efeat = (const float*)d_in[3];
    const float* f     = (const float*)d_in[4];
    const float* W1    = (const float*)d_in[5];
    const float* b1    = (const float*)d_in[6];
    const float* W2    = (const float*)d_in[7];
    const float* b2    = (const float*)d_in[8];
    float* out = (float*)d_out;

    int E = in_sizes[0];          // 160000
    int N = in_sizes[4] / 48;     // f is (N,16,3) -> 10000

    cudaFuncSetAttribute(passA, cudaFuncAttributeMaxDynamicSharedMemorySize, SMEM_BYTES);

    initK<<<(N * 24 + 255) / 256, 256>>>(out, N);

    int ntiles = (E + 31) / 32;
    int grid = ntiles < 148 ? ntiles : 148;
    passA<<<grid, NTHR, SMEM_BYTES>>>(src, dst, basis, efeat, f, W1, b1, W2, b2, E);

    passB<<<(E * 8 + 255) / 256, 256>>>(dst, out, E);
}

// round 13
// speedup vs baseline: 2.2804x; 1.3358x over previous
#include <cuda_runtime.h>
#include <cuda_bf16.h>

// Problem constants (fixed per metadata)
#define EMAX 160000
#define NMAX 10000

// Scratch (device globals — allocation-free)
__device__ float g_ex[EMAX * 4];      // exp(score) per edge/head
__device__ float g_v[EMAX * 24];      // v per edge (m2*d2 = 24)
__device__ float g_denom[NMAX * 4];   // softmax denominator per node/head

// Packed fp32x2 FMA (Blackwell)
#define FMA_F32X2(d, a, b) \
    asm("fma.rn.f32x2 %0, %1, %2, %0;" : "+l"(d) : "l"(a), "l"(b))
#define PACK_F32X2(out, lo, hi) \
    asm("mov.b64 %0, {%1, %2};" : "=l"(out) : "f"(lo), "f"(hi))

// m16n8k16 bf16 MMA, fp32 accumulate (register tensor-core path)
__device__ __forceinline__ void mma_bf16(float d[4], const unsigned a[4],
                                         unsigned b0, unsigned b1) {
    asm volatile(
        "mma.sync.aligned.m16n8k16.row.col.f32.bf16.bf16.f32 "
        "{%0,%1,%2,%3},{%4,%5,%6,%7},{%8,%9},{%0,%1,%2,%3};"
        : "+f"(d[0]), "+f"(d[1]), "+f"(d[2]), "+f"(d[3])
        : "r"(a[0]), "r"(a[1]), "r"(a[2]), "r"(a[3]), "r"(b0), "r"(b1));
}
__device__ __forceinline__ void ldsm_x4(unsigned r[4], unsigned addr) {
    asm volatile("ldmatrix.sync.aligned.m8n8.x4.shared.b16 {%0,%1,%2,%3}, [%4];"
        : "=r"(r[0]), "=r"(r[1]), "=r"(r[2]), "=r"(r[3]) : "r"(addr));
}

// Shared memory layout (byte offsets)
#define SM_W2HI 0        // [768 o][64 k] bf16 hi, 128B rows, 16B-octet XOR swizzle (98304)
#define SM_W2LO 98304    // bf16 lo plane                                           (98304)
#define SM_W1   196608   // [64][32] fp32                                           (8192)
#define SM_HHI  204800   // [32 e][64 k] bf16 hi, 128B rows, octet swizzle          (4096)
#define SM_HLO  208896   // bf16 lo plane                                           (4096)
#define SM_UNI  212992   // union: bas(2304B)+fg(6144B)+EF[32][34](4352B) = 12800B
                         //        then tmp[32][96] f32 (12288B) then conv[32][72]
#define SM_IDX  225792   // src[32], dst[32]                                        (256)
#define SMEM_BYTES 226048

#define NTHR 256

__global__ __launch_bounds__(NTHR, 1)
void passA(const int* __restrict__ src, const int* __restrict__ dst,
           const float* __restrict__ basis, const float* __restrict__ efeat,
           const float* __restrict__ f, const float* __restrict__ W1,
           const float* __restrict__ b1, const float* __restrict__ W2,
           const float* __restrict__ b2, int E)
{
    extern __shared__ char smc[];
    float* W1s  = (float*)(smc + SM_W1);
    float* uniF = (float*)(smc + SM_UNI);
    float* bas  = uniF;            // 576 floats
    float* fg   = uniF + 576;      // 1536 floats
    float* efs  = uniF + 2112;     // [32][34] floats
    float* tmpf = uniF;            // [32][96] after repurpose
    float* conv = uniF;            // [32][72] after second repurpose
    int* srcs   = (int*)(smc + SM_IDX);
    int* dsts   = (int*)(smc + SM_IDX + 128);
    const unsigned sbase = (unsigned)__cvta_generic_to_shared(smc);

    const int t = threadIdx.x;
    const int w = t >> 5, lane = t & 31;
    const int gid = lane >> 2, tig = lane & 3;

    // ldmatrix lane-address constants
    const int sel   = lane >> 3;
    const int arow  = (lane & 7) + ((sel & 1) << 3);  // A: row within 16-block
    const int ahalf = sel >> 1;                        // A: k-octet half
    const int bnb   = lane >> 4;                       // B: which 8-o block of pair
    const int bhalf = (lane >> 3) & 1;                 // B: k-octet half
    const int brow  = lane & 7;                        // B: o row within 8

    // ---- one-time per block: W2 -> bf16 hi/lo (octet-swizzled), W1 fp32 ----
    for (int idx = t; idx < 768 * 64; idx += NTHR) {
        int o = idx >> 6, k = idx & 63;
        float wv = W2[idx];
        __nv_bfloat16 hb = __float2bfloat16(wv);
        __nv_bfloat16 lb = __float2bfloat16(wv - __bfloat162float(hb));
        int off = o * 128 + (((k >> 3) ^ (o & 7)) << 4) + ((k & 7) << 1);
        *(unsigned short*)(smc + SM_W2HI + off) = __bfloat16_as_ushort(hb);
        *(unsigned short*)(smc + SM_W2LO + off) = __bfloat16_as_ushort(lb);
    }
    for (int idx = t; idx < 2048; idx += NTHR) W1s[idx] = W1[idx];

    // ---- prefetch registers & helpers ----
    const int pf_e  = t >> 3;              // EF row this thread prefetches
    const int pf_io = (t & 7) * 4;         // EF col base (float4)
    int   pf_src, pf_dst;                  // (valid for t<32)
    float4 nef;
    float nb0, nb1, nb2;
    int   nsrcv[6];
    float nfg[6];

    const int ntiles = (E + 31) >> 5;

    // ---- prologue: prefetch first tile ----
    {
        const int eg0n = blockIdx.x << 5;
        if (t < 32) {
            int ee = min(eg0n + t, E - 1);
            pf_src = __ldg(&src[ee]);
            pf_dst = __ldg(&dst[ee]);
        }
        {
            int ee = min(eg0n + pf_e, E - 1);
            nef = __ldg((const float4*)(efeat + ee * 32 + pf_io));
        }
        nb0 = __ldg(&basis[min(eg0n + t / 18,         E - 1) * 18 + (t % 18)]);
        nb1 = __ldg(&basis[min(eg0n + (t + 256) / 18, E - 1) * 18 + ((t + 256) % 18)]);
        if (t < 64)
            nb2 = __ldg(&basis[min(eg0n + (t + 512) / 18, E - 1) * 18 + ((t + 512) % 18)]);
        #pragma unroll
        for (int r = 0; r < 6; r++) {
            int idx = t + 256 * r;
            nsrcv[r] = __ldg(&src[min(eg0n + idx / 48, E - 1)]);
        }
        #pragma unroll
        for (int r = 0; r < 6; r++) {
            int idx = t + 256 * r;
            nfg[r] = __ldg(&f[nsrcv[r] * 48 + idx % 48]);
        }
    }

    for (int tile = blockIdx.x; tile < ntiles; tile += gridDim.x) {
        const int eg0 = tile << 5;

        // ---- stage 1+2: write prefetched data to smem ----
        if (t < 32) { srcs[t] = pf_src; dsts[t] = pf_dst; }
        {
            float* p = efs + pf_e * 34 + pf_io;
            p[0] = nef.x; p[1] = nef.y; p[2] = nef.z; p[3] = nef.w;
        }
        bas[t] = nb0;
        bas[t + 256] = nb1;
        if (t < 64) bas[t + 512] = nb2;
        #pragma unroll
        for (int r = 0; r < 6; r++) fg[t + 256 * r] = nfg[r];
        __syncthreads();

        // ---- issue prefetch part A for next tile (idx, EF, basis, gather srcs) ----
        {
            int tn = tile + gridDim.x; if (tn >= ntiles) tn = tile;
            const int eg0n = tn << 5;
            if (t < 32) {
                int ee = min(eg0n + t, E - 1);
                pf_src = __ldg(&src[ee]);
                pf_dst = __ldg(&dst[ee]);
            }
            {
                int ee = min(eg0n + pf_e, E - 1);
                nef = __ldg((const float4*)(efeat + ee * 32 + pf_io));
            }
            nb0 = __ldg(&basis[min(eg0n + t / 18,         E - 1) * 18 + (t % 18)]);
            nb1 = __ldg(&basis[min(eg0n + (t + 256) / 18, E - 1) * 18 + ((t + 256) % 18)]);
            if (t < 64)
                nb2 = __ldg(&basis[min(eg0n + (t + 512) / 18, E - 1) * 18 + ((t + 512) % 18)]);
            #pragma unroll
            for (int r = 0; r < 6; r++) {
                int idx = t + 256 * r;
                nsrcv[r] = __ldg(&src[min(eg0n + idx / 48, E - 1)]);
            }
        }

        // ---- stage 3a: tmp values into regs (e = t>>3 owns m-group t&7) ----
        float tv[12];
        {
            int e = t >> 3, mg = t & 7;
            #pragma unroll
            for (int mm = 0; mm < 4; mm++) {
                int m = mg * 4 + mm, m1 = m >> 1, rep = m & 1;
                #pragma unroll
                for (int d = 0; d < 3; d++) {
                    float s = 0.f;
                    #pragma unroll
                    for (int d1 = 0; d1 < 3; d1++)
                        s += fg[e * 48 + m1 * 3 + d1] * bas[e * 18 + d1 * 6 + rep * 3 + d];
                    tv[mm * 3 + d] = s;
                }
            }
        }
        // ---- stage 3b: MLP (f32x2, vectorized W1 reads) -> bf16 hi/lo packs ----
        unsigned hip[4], lop[4];
        {
            int e = lane, jg = w;
            unsigned long long ef[16];
            #pragma unroll
            for (int p = 0; p < 16; p++)
                ef[p] = *(const unsigned long long*)(efs + e * 34 + p * 2);
            float hv[8];
            #pragma unroll
            for (int jj = 0; jj < 8; jj++) {
                int j = jg * 8 + jj;
                const float* wrow = W1s + j * 32;
                unsigned long long acc = 0ull;
                #pragma unroll
                for (int p4 = 0; p4 < 8; p4++) {
                    ulonglong2 wq = *(const ulonglong2*)(wrow + p4 * 4);
                    FMA_F32X2(acc, ef[2 * p4],     wq.x);
                    FMA_F32X2(acc, ef[2 * p4 + 1], wq.y);
                }
                float h = __uint_as_float((unsigned)acc)
                        + __uint_as_float((unsigned)(acc >> 32)) + __ldg(&b1[j]);
                hv[jj] = fmaxf(h, 0.f);
            }
            #pragma unroll
            for (int q2 = 0; q2 < 4; q2++) {
                __nv_bfloat16 h0 = __float2bfloat16(hv[q2 * 2]);
                __nv_bfloat16 h1 = __float2bfloat16(hv[q2 * 2 + 1]);
                __nv_bfloat16 l0 = __float2bfloat16(hv[q2 * 2]     - __bfloat162float(h0));
                __nv_bfloat16 l1 = __float2bfloat16(hv[q2 * 2 + 1] - __bfloat162float(h1));
                hip[q2] = (unsigned)__bfloat16_as_ushort(h0) | ((unsigned)__bfloat16_as_ushort(h1) << 16);
                lop[q2] = (unsigned)__bfloat16_as_ushort(l0) | ((unsigned)__bfloat16_as_ushort(l1) << 16);
            }
        }
        __syncthreads();   // bas/fg/efs reads done -> union may be overwritten

        // ---- stage 4a: write tmp (pair-swizzled) and H hi/lo planes ----
        {
            int e = t >> 3, mg = t & 7;
            #pragma unroll
            for (int mm = 0; mm < 4; mm++) {
                int m = mg * 4 + mm, mp = m >> 1;
                #pragma unroll
                for (int d = 0; d < 3; d++)
                    tmpf[e * 96 + d * 32 + (((mp ^ (e & 7)) << 1) | (m & 1))] = tv[mm * 3 + d];
            }
        }
        {
            int e = lane, jg = w;
            int off = e * 128 + ((jg ^ (e & 7)) << 4);
            *(uint4*)(smc + SM_HHI + off) = make_uint4(hip[0], hip[1], hip[2], hip[3]);
            *(uint4*)(smc + SM_HLO + off) = make_uint4(lop[0], lop[1], lop[2], lop[3]);
        }
        __syncthreads();

        // ---- stage 4b: HMMA GEMM (3-term bf16 split), warp w owns o=[96w,96w+96) ----
        float D[2][12][4];
        #pragma unroll
        for (int nb = 0; nb < 12; nb++) {
            float2 bb = __ldg((const float2*)(b2 + w * 96 + nb * 8 + tig * 2));
            #pragma unroll
            for (int eb = 0; eb < 2; eb++) {
                D[eb][nb][0] = bb.x; D[eb][nb][1] = bb.y;
                D[eb][nb][2] = bb.x; D[eb][nb][3] = bb.y;
            }
        }
        {
            unsigned browoff = (unsigned)((w * 96 + bnb * 8 + brow) * 128);
            #pragma unroll
            for (int K = 0; K < 4; K++) {
                unsigned ah[2][4], al[2][4];
                #pragma unroll
                for (int eb = 0; eb < 2; eb++) {
                    unsigned rowoff = (unsigned)((eb * 16 + arow) * 128);
                    unsigned oct = (unsigned)(((2 * K + ahalf) ^ (lane & 7)) << 4);
                    ldsm_x4(ah[eb], sbase + SM_HHI + rowoff + oct);
                    ldsm_x4(al[eb], sbase + SM_HLO + rowoff + oct);
                }
                unsigned octb = (unsigned)(((2 * K + bhalf) ^ brow) << 4);
                #pragma unroll
                for (int pr = 0; pr < 6; pr++) {
                    unsigned off = browoff + (unsigned)(pr * 2048) + octb;  // 16 rows*128B
                    unsigned bh[4], bl[4];
                    ldsm_x4(bh, sbase + SM_W2HI + off);
                    ldsm_x4(bl, sbase + SM_W2LO + off);
                    #pragma unroll
                    for (int eb = 0; eb < 2; eb++) {
                        mma_bf16(D[eb][2 * pr],     ah[eb], bh[0], bh[1]);
                        mma_bf16(D[eb][2 * pr],     al[eb], bh[0], bh[1]);
                        mma_bf16(D[eb][2 * pr],     ah[eb], bl[0], bl[1]);
                        mma_bf16(D[eb][2 * pr + 1], ah[eb], bh[2], bh[3]);
                        mma_bf16(D[eb][2 * pr + 1], al[eb], bh[2], bh[3]);
                        mma_bf16(D[eb][2 * pr + 1], ah[eb], bl[2], bl[3]);
                    }
                }
            }
        }

        // ---- issue prefetch part B for next tile (gathered f; srcs arrived) ----
        #pragma unroll
        for (int r = 0; r < 6; r++) {
            int idx = t + 256 * r;
            nfg[r] = __ldg(&f[nsrcv[r] * 48 + idx % 48]);
        }

        // ---- epilogue: conv[e][c][d] = sum_m rw[e][c][m]*tmp[e][m][d] ----
        float pc[2][2][3][3];   // [eb][h][ci][d]
        #pragma unroll
        for (int eb = 0; eb < 2; eb++)
            #pragma unroll
            for (int h = 0; h < 2; h++) {
                int e_l = eb * 16 + h * 8 + gid;       // e&7 == gid
                unsigned long long tp[3][4];
                #pragma unroll
                for (int d = 0; d < 3; d++)
                    #pragma unroll
                    for (int j = 0; j < 4; j++) {
                        int mp = j * 4 + tig;
                        tp[d][j] = *(const unsigned long long*)
                            (tmpf + e_l * 96 + d * 32 + ((mp ^ gid) << 1));
                    }
                unsigned long long acc[3][3];
                #pragma unroll
                for (int ci = 0; ci < 3; ci++)
                    #pragma unroll
                    for (int d = 0; d < 3; d++)
                        acc[ci][d] = 0ull;
                #pragma unroll
                for (int ci = 0; ci < 3; ci++)
                    #pragma unroll
                    for (int j = 0; j < 4; j++) {
                        unsigned long long pd;
                        PACK_F32X2(pd, D[eb][ci * 4 + j][h * 2], D[eb][ci * 4 + j][h * 2 + 1]);
                        #pragma unroll
                        for (int d = 0; d < 3; d++)
                            FMA_F32X2(acc[ci][d], pd, tp[d][j]);
                    }
                #pragma unroll
                for (int ci = 0; ci < 3; ci++)
                    #pragma unroll
                    for (int d = 0; d < 3; d++)
                        pc[eb][h][ci][d] = __uint_as_float((unsigned)acc[ci][d])
                                         + __uint_as_float((unsigned)(acc[ci][d] >> 32));
            }
        // reduce m-partials across tig (lane bits 0-1)
        #pragma unroll
        for (int off = 1; off < 4; off <<= 1)
            #pragma unroll
            for (int eb = 0; eb < 2; eb++)
                #pragma unroll
                for (int h = 0; h < 2; h++)
                    #pragma unroll
                    for (int ci = 0; ci < 3; ci++)
                        #pragma unroll
                        for (int d = 0; d < 3; d++)
                            pc[eb][h][ci][d] += __shfl_xor_sync(0xffffffffu, pc[eb][h][ci][d], off);
        __syncthreads();   // ALL tmp reads complete before conv overwrites union
        if (tig == 0) {
            #pragma unroll
            for (int eb = 0; eb < 2; eb++)
                #pragma unroll
                for (int h = 0; h < 2; h++) {
                    int e_l = eb * 16 + h * 8 + gid;
                    #pragma unroll
                    for (int ci = 0; ci < 3; ci++) {
                        int c = w * 3 + ci;
                        #pragma unroll
                        for (int d = 0; d < 3; d++)
                            conv[e_l * 72 + c * 3 + d] = pc[eb][h][ci][d];
                    }
                }
        }
        __syncthreads();

        // ---- stage 5: attention scores, exp, denom atomics, stash v ----
        {
            int e = t >> 3, s = t & 7;
            int ge = eg0 + e;
            if (ge < E) {
                if (s < 4) {
                    float sc = 0.f;
                    #pragma unroll
                    for (int hd = 0; hd < 6; hd++)
                        sc += conv[e * 72 + s * 6 + hd] * conv[e * 72 + 24 + s * 6 + hd];
                    sc *= 0.20412414523193154f;           // 24^-0.5
                    sc = (sc >= 0.f) ? sc : 0.2f * sc;    // leaky_relu(0.2)
                    float ex = __expf(sc);                // shift-invariant softmax
                    g_ex[ge * 4 + s] = ex;
                    atomicAdd(&g_denom[dsts[e] * 4 + s], ex);
                }
                #pragma unroll
                for (int jj = 0; jj < 3; jj++)
                    g_v[ge * 24 + s * 3 + jj] = conv[e * 72 + 48 + s * 3 + jj];
            }
        }
        __syncthreads();
    }
}

__global__ void initK(float* __restrict__ out, int N)
{
    int i = blockIdx.x * blockDim.x + threadIdx.x;
    if (i < N * 24) out[i] = 0.f;
    if (i < N * 4)  g_denom[i] = 0.f;
}

__global__ __launch_bounds__(256)
void passB(const int* __restrict__ dst, float* __restrict__ out, int E)
{
    int idx = blockIdx.x * blockDim.x + threadIdx.x;
    int e = idx >> 3, s = idx & 7;      // 8 threads/edge, 3 outputs each
    if (e >= E) return;
    int d = dst[e];
    int head = s >> 1;                   // 6 floats/head, 3 per thread
    float wgt = g_ex[e * 4 + head] / g_denom[d * 4 + head];
    #pragma unroll
    for (int jj = 0; jj < 3; jj++) {
        int j = s * 3 + jj;
        atomicAdd(&out[d * 24 + j], wgt * g_v[e * 24 + j]);
    }
}

extern "C" void kernel_launch(void* const* d_in, const int* in_sizes, int n_in,
                              void* d_out, int out_size)
{
    const int*   src   = (const int*)d_in[0];
    const int*   dst   = (const int*)d_in[1];
    const float* basis = (const float*)d_in[2];
    const float* efeat = (const float*)d_in[3];
    const float* f     = (const float*)d_in[4];
    const float* W1    = (const float*)d_in[5];
    const float* b1    = (const float*)d_in[6];
    const float* W2    = (const float*)d_in[7];
    const float* b2    = (const float*)d_in[8];
    float* out = (float*)d_out;

    int E = in_sizes[0];          // 160000
    int N = in_sizes[4] / 48;     // f is (N,16,3) -> 10000

    cudaFuncSetAttribute(passA, cudaFuncAttributeMaxDynamicSharedMemorySize, SMEM_BYTES);

    initK<<<(N * 24 + 255) / 256, 256>>>(out, N);

    int ntiles = (E + 31) / 32;
    int grid = ntiles < 148 ? ntiles : 148;
    passA<<<grid, NTHR, SMEM_BYTES>>>(src, dst, basis, efeat, f, W1, b1, W2, b2, E);

    passB<<<(E * 8 + 255) / 256, 256>>>(dst, out, E);
}

// round 14
// speedup vs baseline: 2.2857x; 1.0023x over previous
#include <cuda_runtime.h>
#include <cuda_bf16.h>

// Problem constants (fixed per metadata)
#define EMAX 160000
#define NMAX 10000

// Scratch (device globals — allocation-free)
__device__ float g_ex[EMAX * 4];      // exp(score) per edge/head
__device__ float g_v[EMAX * 24];      // v per edge (m2*d2 = 24)
__device__ float g_denom[NMAX * 4];   // softmax denominator per node/head

// Packed fp32x2 FMA (Blackwell)
#define FMA_F32X2(d, a, b) \
    asm("fma.rn.f32x2 %0, %1, %2, %0;" : "+l"(d) : "l"(a), "l"(b))
#define PACK_F32X2(out, lo, hi) \
    asm("mov.b64 %0, {%1, %2};" : "=l"(out) : "f"(lo), "f"(hi))

// m16n8k16 bf16 MMA, fp32 accumulate (register tensor-core path)
__device__ __forceinline__ void mma_bf16(float d[4], const unsigned a[4],
                                         unsigned b0, unsigned b1) {
    asm volatile(
        "mma.sync.aligned.m16n8k16.row.col.f32.bf16.bf16.f32 "
        "{%0,%1,%2,%3},{%4,%5,%6,%7},{%8,%9},{%0,%1,%2,%3};"
        : "+f"(d[0]), "+f"(d[1]), "+f"(d[2]), "+f"(d[3])
        : "r"(a[0]), "r"(a[1]), "r"(a[2]), "r"(a[3]), "r"(b0), "r"(b1));
}
__device__ __forceinline__ void ldsm_x4(unsigned r[4], unsigned addr) {
    asm volatile("ldmatrix.sync.aligned.m8n8.x4.shared.b16 {%0,%1,%2,%3}, [%4];"
        : "=r"(r[0]), "=r"(r[1]), "=r"(r[2]), "=r"(r[3]) : "r"(addr));
}

// Shared memory layout (byte offsets)
#define SM_W2HI 0        // [768 o][64 k] bf16 hi, 128B rows, 16B-octet XOR swizzle (98304)
#define SM_W2LO 98304    // bf16 lo plane                                           (98304)
#define SM_W1   196608   // [64][32] fp32                                           (8192)
#define SM_HHI  204800   // [32 e][64 k] bf16 hi, 128B rows, octet swizzle          (4096)
#define SM_HLO  208896   // bf16 lo plane                                           (4096)
#define SM_UNI  212992   // union: bas(2304B)+fg(6144B)+EF[32][34](4352B) = 12800B
                         //        then tmp[32][96] f32 (12288B) then conv[32][72]
#define SM_IDX  225792   // src[32], dst[32]                                        (256)
#define SMEM_BYTES 226048

#define NTHR 256

__global__ __launch_bounds__(NTHR, 1)
void passA(const int* __restrict__ src, const int* __restrict__ dst,
           const float* __restrict__ basis, const float* __restrict__ efeat,
           const float* __restrict__ f, const float* __restrict__ W1,
           const float* __restrict__ b1, const float* __restrict__ W2,
           const float* __restrict__ b2, int E)
{
    extern __shared__ char smc[];
    float* W1s  = (float*)(smc + SM_W1);
    float* uniF = (float*)(smc + SM_UNI);
    float* bas  = uniF;            // 576 floats
    float* fg   = uniF + 576;      // 1536 floats
    float* efs  = uniF + 2112;     // [32][34] floats
    float* tmpf = uniF;            // [32][96] after repurpose
    float* conv = uniF;            // [32][72] after second repurpose
    int* srcs   = (int*)(smc + SM_IDX);
    int* dsts   = (int*)(smc + SM_IDX + 128);
    const unsigned sbase = (unsigned)__cvta_generic_to_shared(smc);

    const int t = threadIdx.x;
    const int w = t >> 5, lane = t & 31;
    const int gid = lane >> 2, tig = lane & 3;

    // ldmatrix lane-address constants
    const int sel   = lane >> 3;
    const int arow  = (lane & 7) + ((sel & 1) << 3);  // A: row within 16-block
    const int ahalf = sel >> 1;                        // A: k-octet half
    const int bnb   = lane >> 4;                       // B: which 8-o block of pair
    const int bhalf = (lane >> 3) & 1;                 // B: k-octet half
    const int brow  = lane & 7;                        // B: o row within 8

    // ---- one-time per block: W2 -> bf16 hi/lo (octet-swizzled), W1 fp32 ----
    for (int idx = t; idx < 768 * 64; idx += NTHR) {
        int o = idx >> 6, k = idx & 63;
        float wv = W2[idx];
        __nv_bfloat16 hb = __float2bfloat16(wv);
        __nv_bfloat16 lb = __float2bfloat16(wv - __bfloat162float(hb));
        int off = o * 128 + (((k >> 3) ^ (o & 7)) << 4) + ((k & 7) << 1);
        *(unsigned short*)(smc + SM_W2HI + off) = __bfloat16_as_ushort(hb);
        *(unsigned short*)(smc + SM_W2LO + off) = __bfloat16_as_ushort(lb);
    }
    for (int idx = t; idx < 2048; idx += NTHR) W1s[idx] = W1[idx];

    // ---- prefetch registers & helpers ----
    const int pf_e  = t >> 3;              // EF row this thread prefetches
    const int pf_io = (t & 7) * 4;         // EF col base (float4)
    int   pf_src, pf_dst;                  // (valid for t<32)
    float4 nef;
    float nb0, nb1, nb2;
    int   nsrcv[6];
    float nfg[6];

    const int ntiles = (E + 31) >> 5;

    // ---- prologue: prefetch first tile ----
    {
        const int eg0n = blockIdx.x << 5;
        if (t < 32) {
            int ee = min(eg0n + t, E - 1);
            pf_src = __ldg(&src[ee]);
            pf_dst = __ldg(&dst[ee]);
        }
        {
            int ee = min(eg0n + pf_e, E - 1);
            nef = __ldg((const float4*)(efeat + ee * 32 + pf_io));
        }
        nb0 = __ldg(&basis[min(eg0n + t / 18,         E - 1) * 18 + (t % 18)]);
        nb1 = __ldg(&basis[min(eg0n + (t + 256) / 18, E - 1) * 18 + ((t + 256) % 18)]);
        if (t < 64)
            nb2 = __ldg(&basis[min(eg0n + (t + 512) / 18, E - 1) * 18 + ((t + 512) % 18)]);
        #pragma unroll
        for (int r = 0; r < 6; r++) {
            int idx = t + 256 * r;
            nsrcv[r] = __ldg(&src[min(eg0n + idx / 48, E - 1)]);
        }
        #pragma unroll
        for (int r = 0; r < 6; r++) {
            int idx = t + 256 * r;
            nfg[r] = __ldg(&f[nsrcv[r] * 48 + idx % 48]);
        }
    }

    for (int tile = blockIdx.x; tile < ntiles; tile += gridDim.x) {
        const int eg0 = tile << 5;

        // ---- stage 1+2: write prefetched data to smem ----
        if (t < 32) { srcs[t] = pf_src; dsts[t] = pf_dst; }
        {
            float* p = efs + pf_e * 34 + pf_io;
            p[0] = nef.x; p[1] = nef.y; p[2] = nef.z; p[3] = nef.w;
        }
        bas[t] = nb0;
        bas[t + 256] = nb1;
        if (t < 64) bas[t + 512] = nb2;
        #pragma unroll
        for (int r = 0; r < 6; r++) fg[t + 256 * r] = nfg[r];
        __syncthreads();

        // ---- issue prefetch part A for next tile (idx, EF, basis, gather srcs) ----
        {
            int tn = tile + gridDim.x; if (tn >= ntiles) tn = tile;
            const int eg0n = tn << 5;
            if (t < 32) {
                int ee = min(eg0n + t, E - 1);
                pf_src = __ldg(&src[ee]);
                pf_dst = __ldg(&dst[ee]);
            }
            {
                int ee = min(eg0n + pf_e, E - 1);
                nef = __ldg((const float4*)(efeat + ee * 32 + pf_io));
            }
            nb0 = __ldg(&basis[min(eg0n + t / 18,         E - 1) * 18 + (t % 18)]);
            nb1 = __ldg(&basis[min(eg0n + (t + 256) / 18, E - 1) * 18 + ((t + 256) % 18)]);
            if (t < 64)
                nb2 = __ldg(&basis[min(eg0n + (t + 512) / 18, E - 1) * 18 + ((t + 512) % 18)]);
            #pragma unroll
            for (int r = 0; r < 6; r++) {
                int idx = t + 256 * r;
                nsrcv[r] = __ldg(&src[min(eg0n + idx / 48, E - 1)]);
            }
        }

        // ---- stage 3a: tmp values into regs (e = t>>3 owns m-group t&7) ----
        float tv[12];
        {
            int e = t >> 3, mg = t & 7;
            #pragma unroll
            for (int mm = 0; mm < 4; mm++) {
                int m = mg * 4 + mm, m1 = m >> 1, rep = m & 1;
                #pragma unroll
                for (int d = 0; d < 3; d++) {
                    float s = 0.f;
                    #pragma unroll
                    for (int d1 = 0; d1 < 3; d1++)
                        s += fg[e * 48 + m1 * 3 + d1] * bas[e * 18 + d1 * 6 + rep * 3 + d];
                    tv[mm * 3 + d] = s;
                }
            }
        }
        // ---- stage 3b: MLP (f32x2, vectorized W1 reads) -> bf16 hi/lo packs ----
        unsigned hip[4], lop[4];
        {
            int e = lane, jg = w;
            unsigned long long ef[16];
            #pragma unroll
            for (int p = 0; p < 16; p++)
                ef[p] = *(const unsigned long long*)(efs + e * 34 + p * 2);
            float hv[8];
            #pragma unroll
            for (int jj = 0; jj < 8; jj++) {
                int j = jg * 8 + jj;
                const float* wrow = W1s + j * 32;
                unsigned long long acc = 0ull;
                #pragma unroll
                for (int p4 = 0; p4 < 8; p4++) {
                    ulonglong2 wq = *(const ulonglong2*)(wrow + p4 * 4);
                    FMA_F32X2(acc, ef[2 * p4],     wq.x);
                    FMA_F32X2(acc, ef[2 * p4 + 1], wq.y);
                }
                float h = __uint_as_float((unsigned)acc)
                        + __uint_as_float((unsigned)(acc >> 32)) + __ldg(&b1[j]);
                hv[jj] = fmaxf(h, 0.f);
            }
            #pragma unroll
            for (int q2 = 0; q2 < 4; q2++) {
                __nv_bfloat16 h0 = __float2bfloat16(hv[q2 * 2]);
                __nv_bfloat16 h1 = __float2bfloat16(hv[q2 * 2 + 1]);
                __nv_bfloat16 l0 = __float2bfloat16(hv[q2 * 2]     - __bfloat162float(h0));
                __nv_bfloat16 l1 = __float2bfloat16(hv[q2 * 2 + 1] - __bfloat162float(h1));
                hip[q2] = (unsigned)__bfloat16_as_ushort(h0) | ((unsigned)__bfloat16_as_ushort(h1) << 16);
                lop[q2] = (unsigned)__bfloat16_as_ushort(l0) | ((unsigned)__bfloat16_as_ushort(l1) << 16);
            }
        }
        __syncthreads();   // bas/fg/efs reads done -> union may be overwritten

        // ---- stage 4a: write tmp (pair-swizzled) and H hi/lo planes ----
        {
            int e = t >> 3, mg = t & 7;
            #pragma unroll
            for (int mm = 0; mm < 4; mm++) {
                int m = mg * 4 + mm, mp = m >> 1;
                #pragma unroll
                for (int d = 0; d < 3; d++)
                    tmpf[e * 96 + d * 32 + (((mp ^ (e & 7)) << 1) | (m & 1))] = tv[mm * 3 + d];
            }
        }
        {
            int e = lane, jg = w;
            int off = e * 128 + ((jg ^ (e & 7)) << 4);
            *(uint4*)(smc + SM_HHI + off) = make_uint4(hip[0], hip[1], hip[2], hip[3]);
            *(uint4*)(smc + SM_HLO + off) = make_uint4(lop[0], lop[1], lop[2], lop[3]);
        }
        __syncthreads();

        // ---- stage 4b: HMMA GEMM (3-term bf16 split), warp w owns o=[96w,96w+96) ----
        float D[2][12][4];
        #pragma unroll
        for (int nb = 0; nb < 12; nb++) {
            float2 bb = __ldg((const float2*)(b2 + w * 96 + nb * 8 + tig * 2));
            #pragma unroll
            for (int eb = 0; eb < 2; eb++) {
                D[eb][nb][0] = bb.x; D[eb][nb][1] = bb.y;
                D[eb][nb][2] = bb.x; D[eb][nb][3] = bb.y;
            }
        }
        {
            unsigned browoff = (unsigned)((w * 96 + bnb * 8 + brow) * 128);
            #pragma unroll
            for (int K = 0; K < 4; K++) {
                unsigned ah[2][4], al[2][4];
                #pragma unroll
                for (int eb = 0; eb < 2; eb++) {
                    unsigned rowoff = (unsigned)((eb * 16 + arow) * 128);
                    unsigned oct = (unsigned)(((2 * K + ahalf) ^ (lane & 7)) << 4);
                    ldsm_x4(ah[eb], sbase + SM_HHI + rowoff + oct);
                    ldsm_x4(al[eb], sbase + SM_HLO + rowoff + oct);
                }
                unsigned octb = (unsigned)(((2 * K + bhalf) ^ brow) << 4);
                #pragma unroll
                for (int pr = 0; pr < 6; pr++) {
                    unsigned off = browoff + (unsigned)(pr * 2048) + octb;  // 16 rows*128B
                    unsigned bh[4], bl[4];
                    ldsm_x4(bh, sbase + SM_W2HI + off);
                    ldsm_x4(bl, sbase + SM_W2LO + off);
                    #pragma unroll
                    for (int eb = 0; eb < 2; eb++) {
                        mma_bf16(D[eb][2 * pr],     ah[eb], bh[0], bh[1]);
                        mma_bf16(D[eb][2 * pr],     al[eb], bh[0], bh[1]);
                        mma_bf16(D[eb][2 * pr],     ah[eb], bl[0], bl[1]);
                        mma_bf16(D[eb][2 * pr + 1], ah[eb], bh[2], bh[3]);
                        mma_bf16(D[eb][2 * pr + 1], al[eb], bh[2], bh[3]);
                        mma_bf16(D[eb][2 * pr + 1], ah[eb], bl[2], bl[3]);
                    }
                }
            }
        }

        // ---- issue prefetch part B for next tile (gathered f; srcs arrived) ----
        #pragma unroll
        for (int r = 0; r < 6; r++) {
            int idx = t + 256 * r;
            nfg[r] = __ldg(&f[nsrcv[r] * 48 + idx % 48]);
        }

        // ---- epilogue: conv[e][c][d] = sum_m rw[e][c][m]*tmp[e][m][d] ----
        float pc[2][2][3][3];   // [eb][h][ci][d]
        #pragma unroll
        for (int eb = 0; eb < 2; eb++)
            #pragma unroll
            for (int h = 0; h < 2; h++) {
                int e_l = eb * 16 + h * 8 + gid;       // e&7 == gid
                unsigned long long tp[3][4];
                #pragma unroll
                for (int d = 0; d < 3; d++)
                    #pragma unroll
                    for (int j = 0; j < 4; j++) {
                        int mp = j * 4 + tig;
                        tp[d][j] = *(const unsigned long long*)
                            (tmpf + e_l * 96 + d * 32 + ((mp ^ gid) << 1));
                    }
                unsigned long long acc[3][3];
                #pragma unroll
                for (int ci = 0; ci < 3; ci++)
                    #pragma unroll
                    for (int d = 0; d < 3; d++)
                        acc[ci][d] = 0ull;
                #pragma unroll
                for (int ci = 0; ci < 3; ci++)
                    #pragma unroll
                    for (int j = 0; j < 4; j++) {
                        unsigned long long pd;
                        PACK_F32X2(pd, D[eb][ci * 4 + j][h * 2], D[eb][ci * 4 + j][h * 2 + 1]);
                        #pragma unroll
                        for (int d = 0; d < 3; d++)
                            FMA_F32X2(acc[ci][d], pd, tp[d][j]);
                    }
                #pragma unroll
                for (int ci = 0; ci < 3; ci++)
                    #pragma unroll
                    for (int d = 0; d < 3; d++)
                        pc[eb][h][ci][d] = __uint_as_float((unsigned)acc[ci][d])
                                         + __uint_as_float((unsigned)(acc[ci][d] >> 32));
            }
        // reduce m-partials across tig (lane bits 0-1)
        #pragma unroll
        for (int off = 1; off < 4; off <<= 1)
            #pragma unroll
            for (int eb = 0; eb < 2; eb++)
                #pragma unroll
                for (int h = 0; h < 2; h++)
                    #pragma unroll
                    for (int ci = 0; ci < 3; ci++)
                        #pragma unroll
                        for (int d = 0; d < 3; d++)
                            pc[eb][h][ci][d] += __shfl_xor_sync(0xffffffffu, pc[eb][h][ci][d], off);
        __syncthreads();   // ALL tmp reads complete before conv overwrites union
        if (tig == 0) {
            #pragma unroll
            for (int eb = 0; eb < 2; eb++)
                #pragma unroll
                for (int h = 0; h < 2; h++) {
                    int e_l = eb * 16 + h * 8 + gid;
                    #pragma unroll
                    for (int ci = 0; ci < 3; ci++) {
                        int c = w * 3 + ci;
                        #pragma unroll
                        for (int d = 0; d < 3; d++)
                            conv[e_l * 72 + c * 3 + d] = pc[eb][h][ci][d];
                    }
                }
        }
        __syncthreads();

        // ---- stage 5: attention scores, exp, denom atomics, stash v ----
        {
            int e = t >> 3, s = t & 7;
            int ge = eg0 + e;
            if (ge < E) {
                if (s < 4) {
                    float sc = 0.f;
                    #pragma unroll
                    for (int hd = 0; hd < 6; hd++)
                        sc += conv[e * 72 + s * 6 + hd] * conv[e * 72 + 24 + s * 6 + hd];
                    sc *= 0.20412414523193154f;           // 24^-0.5
                    sc = (sc >= 0.f) ? sc : 0.2f * sc;    // leaky_relu(0.2)
                    float ex = __expf(sc);                // shift-invariant softmax
                    g_ex[ge * 4 + s] = ex;
                    atomicAdd(&g_denom[dsts[e] * 4 + s], ex);
                }
                #pragma unroll
                for (int jj = 0; jj < 3; jj++)
                    g_v[ge * 24 + s * 3 + jj] = conv[e * 72 + 48 + s * 3 + jj];
            }
        }
        __syncthreads();
    }
}

__global__ void initK(float* __restrict__ out, int N)
{
    int i = blockIdx.x * blockDim.x + threadIdx.x;
    if (i < N * 24) out[i] = 0.f;
    if (i < N * 4)  g_denom[i] = 0.f;
}

__global__ __launch_bounds__(256)
void passB(const int* __restrict__ dst, float* __restrict__ out, int E)
{
    int idx = blockIdx.x * blockDim.x + threadIdx.x;
    int e = idx >> 3, s = idx & 7;      // 8 threads/edge, 3 outputs each
    if (e >= E) return;
    int d = dst[e];
    int head = s >> 1;                   // 6 floats/head, 3 per thread
    float wgt = g_ex[e * 4 + head] / g_denom[d * 4 + head];
    #pragma unroll
    for (int jj = 0; jj < 3; jj++) {
        int j = s * 3 + jj;
        atomicAdd(&out[d * 24 + j], wgt * g_v[e * 24 + j]);
    }
}

extern "C" void kernel_launch(void* const* d_in, const int* in_sizes, int n_in,
                              void* d_out, int out_size)
{
    const int*   src   = (const int*)d_in[0];
    const int*   dst   = (const int*)d_in[1];
    const float* basis = (const float*)d_in[2];
    const float* efeat = (const float*)d_in[3];
    const float* f     = (const float*)d_in[4];
    const float* W1    = (const float*)d_in[5];
    const float* b1    = (const float*)d_in[6];
    const float* W2    = (const float*)d_in[7];
    const float* b2    = (const float*)d_in[8];
    float* out = (float*)d_out;

    int E = in_sizes[0];          // 160000
    int N = in_sizes[4] / 48;     // f is (N,16,3) -> 10000

    cudaFuncSetAttribute(passA, cudaFuncAttributeMaxDynamicSharedMemorySize, SMEM_BYTES);

    initK<<<(N * 24 + 255) / 256, 256>>>(out, N);

    int ntiles = (E + 31) / 32;
    int grid = ntiles < 148 ? ntiles : 148;
    passA<<<grid, NTHR, SMEM_BYTES>>>(src, dst, basis, efeat, f, W1, b1, W2, b2, E);

    passB<<<(E * 8 + 255) / 256, 256>>>(dst, out, E);
}

// round 15
// speedup vs baseline: 2.2870x; 1.0005x over previous
#include <cuda_runtime.h>
#include <cuda_bf16.h>

// Problem constants (fixed per metadata)
#define EMAX 160000
#define NMAX 10000

// Scratch (device globals — allocation-free)
__device__ float g_ex[EMAX * 4];      // exp(score) per edge/head
__device__ float g_v[EMAX * 24];      // v per edge (m2*d2 = 24)
__device__ float g_denom[NMAX * 4];   // softmax denominator per node/head

// Packed fp32x2 FMA (Blackwell)
#define FMA_F32X2(d, a, b) \
    asm("fma.rn.f32x2 %0, %1, %2, %0;" : "+l"(d) : "l"(a), "l"(b))
#define PACK_F32X2(out, lo, hi) \
    asm("mov.b64 %0, {%1, %2};" : "=l"(out) : "f"(lo), "f"(hi))

// m16n8k16 bf16 MMA, fp32 accumulate (register tensor-core path)
__device__ __forceinline__ void mma_bf16(float d[4], const unsigned a[4],
                                         unsigned b0, unsigned b1) {
    asm volatile(
        "mma.sync.aligned.m16n8k16.row.col.f32.bf16.bf16.f32 "
        "{%0,%1,%2,%3},{%4,%5,%6,%7},{%8,%9},{%0,%1,%2,%3};"
        : "+f"(d[0]), "+f"(d[1]), "+f"(d[2]), "+f"(d[3])
        : "r"(a[0]), "r"(a[1]), "r"(a[2]), "r"(a[3]), "r"(b0), "r"(b1));
}
__device__ __forceinline__ void ldsm_x4(unsigned r[4], unsigned addr) {
    asm volatile("ldmatrix.sync.aligned.m8n8.x4.shared.b16 {%0,%1,%2,%3}, [%4];"
        : "=r"(r[0]), "=r"(r[1]), "=r"(r[2]), "=r"(r[3]) : "r"(addr));
}

// Shared memory layout (byte offsets)
#define SM_W2HI 0        // [768 o][64 k] bf16 hi, 128B rows, 16B-octet XOR swizzle (98304)
#define SM_W2LO 98304    // bf16 lo plane                                           (98304)
#define SM_W1   196608   // [64][32] fp32                                           (8192)
#define SM_HHI  204800   // [32 e][64 k] bf16 hi, 128B rows, octet swizzle          (4096)
#define SM_HLO  208896   // bf16 lo plane                                           (4096)
#define SM_UNI  212992   // union: bas(2304B)+fg(6144B)+EF[32][34](4352B) = 12800B
                         //        then tmp[32][96] f32 (12288B) then conv[32][72]
#define SM_IDX  225792   // src[32], dst[32]                                        (256)
#define SMEM_BYTES 226048

#define NTHR 256

__global__ __launch_bounds__(NTHR, 1)
void passA(const int* __restrict__ src, const int* __restrict__ dst,
           const float* __restrict__ basis, const float* __restrict__ efeat,
           const float* __restrict__ f, const float* __restrict__ W1,
           const float* __restrict__ b1, const float* __restrict__ W2,
           const float* __restrict__ b2, int E)
{
    extern __shared__ char smc[];
    float* W1s  = (float*)(smc + SM_W1);
    float* uniF = (float*)(smc + SM_UNI);
    float* bas  = uniF;            // 576 floats
    float* fg   = uniF + 576;      // 1536 floats
    float* efs  = uniF + 2112;     // [32][34] floats
    float* tmpf = uniF;            // [32][96] after repurpose
    float* conv = uniF;            // [32][72] after second repurpose
    int* srcs   = (int*)(smc + SM_IDX);
    int* dsts   = (int*)(smc + SM_IDX + 128);
    const unsigned sbase = (unsigned)__cvta_generic_to_shared(smc);

    const int t = threadIdx.x;
    const int w = t >> 5, lane = t & 31;
    const int gid = lane >> 2, tig = lane & 3;

    // ldmatrix lane-address constants
    const int sel   = lane >> 3;
    const int arow  = (lane & 7) + ((sel & 1) << 3);  // A: row within 16-block
    const int ahalf = sel >> 1;                        // A: k-octet half
    const int bnb   = lane >> 4;                       // B: which 8-o block of pair
    const int bhalf = (lane >> 3) & 1;                 // B: k-octet half
    const int brow  = lane & 7;                        // B: o row within 8

    // ---- one-time per block: W2 -> bf16 hi/lo (octet-swizzled), W1 fp32 ----
    for (int idx = t; idx < 768 * 64; idx += NTHR) {
        int o = idx >> 6, k = idx & 63;
        float wv = W2[idx];
        __nv_bfloat16 hb = __float2bfloat16(wv);
        __nv_bfloat16 lb = __float2bfloat16(wv - __bfloat162float(hb));
        int off = o * 128 + (((k >> 3) ^ (o & 7)) << 4) + ((k & 7) << 1);
        *(unsigned short*)(smc + SM_W2HI + off) = __bfloat16_as_ushort(hb);
        *(unsigned short*)(smc + SM_W2LO + off) = __bfloat16_as_ushort(lb);
    }
    for (int idx = t; idx < 2048; idx += NTHR) W1s[idx] = W1[idx];

    // ---- prefetch registers & helpers ----
    const int pf_e  = t >> 3;              // EF row this thread prefetches
    const int pf_io = (t & 7) * 4;         // EF col base (float4)
    int   pf_src, pf_dst;                  // (valid for t<32)
    float4 nef;
    float nb0, nb1, nb2;
    int   nsrcv[6];
    float nfg[6];

    const int ntiles = (E + 31) >> 5;

    // ---- prologue: prefetch first tile ----
    {
        const int eg0n = blockIdx.x << 5;
        if (t < 32) {
            int ee = min(eg0n + t, E - 1);
            pf_src = __ldg(&src[ee]);
            pf_dst = __ldg(&dst[ee]);
        }
        {
            int ee = min(eg0n + pf_e, E - 1);
            nef = __ldg((const float4*)(efeat + ee * 32 + pf_io));
        }
        nb0 = __ldg(&basis[min(eg0n + t / 18,         E - 1) * 18 + (t % 18)]);
        nb1 = __ldg(&basis[min(eg0n + (t + 256) / 18, E - 1) * 18 + ((t + 256) % 18)]);
        if (t < 64)
            nb2 = __ldg(&basis[min(eg0n + (t + 512) / 18, E - 1) * 18 + ((t + 512) % 18)]);
        #pragma unroll
        for (int r = 0; r < 6; r++) {
            int idx = t + 256 * r;
            nsrcv[r] = __ldg(&src[min(eg0n + idx / 48, E - 1)]);
        }
        #pragma unroll
        for (int r = 0; r < 6; r++) {
            int idx = t + 256 * r;
            nfg[r] = __ldg(&f[nsrcv[r] * 48 + idx % 48]);
        }
    }

    for (int tile = blockIdx.x; tile < ntiles; tile += gridDim.x) {
        const int eg0 = tile << 5;

        // ---- stage 1+2: write prefetched data to smem ----
        if (t < 32) { srcs[t] = pf_src; dsts[t] = pf_dst; }
        {
            float* p = efs + pf_e * 34 + pf_io;
            p[0] = nef.x; p[1] = nef.y; p[2] = nef.z; p[3] = nef.w;
        }
        bas[t] = nb0;
        bas[t + 256] = nb1;
        if (t < 64) bas[t + 512] = nb2;
        #pragma unroll
        for (int r = 0; r < 6; r++) fg[t + 256 * r] = nfg[r];
        __syncthreads();

        // ---- issue prefetch part A for next tile (idx, EF, basis, gather srcs) ----
        {
            int tn = tile + gridDim.x; if (tn >= ntiles) tn = tile;
            const int eg0n = tn << 5;
            if (t < 32) {
                int ee = min(eg0n + t, E - 1);
                pf_src = __ldg(&src[ee]);
                pf_dst = __ldg(&dst[ee]);
            }
            {
                int ee = min(eg0n + pf_e, E - 1);
                nef = __ldg((const float4*)(efeat + ee * 32 + pf_io));
            }
            nb0 = __ldg(&basis[min(eg0n + t / 18,         E - 1) * 18 + (t % 18)]);
            nb1 = __ldg(&basis[min(eg0n + (t + 256) / 18, E - 1) * 18 + ((t + 256) % 18)]);
            if (t < 64)
                nb2 = __ldg(&basis[min(eg0n + (t + 512) / 18, E - 1) * 18 + ((t + 512) % 18)]);
            #pragma unroll
            for (int r = 0; r < 6; r++) {
                int idx = t + 256 * r;
                nsrcv[r] = __ldg(&src[min(eg0n + idx / 48, E - 1)]);
            }
        }

        // ---- stage 3a: tmp values into regs (e = t>>3 owns m-group t&7) ----
        float tv[12];
        {
            int e = t >> 3, mg = t & 7;
            #pragma unroll
            for (int mm = 0; mm < 4; mm++) {
                int m = mg * 4 + mm, m1 = m >> 1, rep = m & 1;
                #pragma unroll
                for (int d = 0; d < 3; d++) {
                    float s = 0.f;
                    #pragma unroll
                    for (int d1 = 0; d1 < 3; d1++)
                        s += fg[e * 48 + m1 * 3 + d1] * bas[e * 18 + d1 * 6 + rep * 3 + d];
                    tv[mm * 3 + d] = s;
                }
            }
        }
        // ---- stage 3b: MLP (f32x2, vectorized W1 reads) -> bf16 hi/lo packs ----
        unsigned hip[4], lop[4];
        {
            int e = lane, jg = w;
            unsigned long long ef[16];
            #pragma unroll
            for (int p = 0; p < 16; p++)
                ef[p] = *(const unsigned long long*)(efs + e * 34 + p * 2);
            float hv[8];
            #pragma unroll
            for (int jj = 0; jj < 8; jj++) {
                int j = jg * 8 + jj;
                const float* wrow = W1s + j * 32;
                unsigned long long acc = 0ull;
                #pragma unroll
                for (int p4 = 0; p4 < 8; p4++) {
                    ulonglong2 wq = *(const ulonglong2*)(wrow + p4 * 4);
                    FMA_F32X2(acc, ef[2 * p4],     wq.x);
                    FMA_F32X2(acc, ef[2 * p4 + 1], wq.y);
                }
                float h = __uint_as_float((unsigned)acc)
                        + __uint_as_float((unsigned)(acc >> 32)) + __ldg(&b1[j]);
                hv[jj] = fmaxf(h, 0.f);
            }
            #pragma unroll
            for (int q2 = 0; q2 < 4; q2++) {
                __nv_bfloat16 h0 = __float2bfloat16(hv[q2 * 2]);
                __nv_bfloat16 h1 = __float2bfloat16(hv[q2 * 2 + 1]);
                __nv_bfloat16 l0 = __float2bfloat16(hv[q2 * 2]     - __bfloat162float(h0));
                __nv_bfloat16 l1 = __float2bfloat16(hv[q2 * 2 + 1] - __bfloat162float(h1));
                hip[q2] = (unsigned)__bfloat16_as_ushort(h0) | ((unsigned)__bfloat16_as_ushort(h1) << 16);
                lop[q2] = (unsigned)__bfloat16_as_ushort(l0) | ((unsigned)__bfloat16_as_ushort(l1) << 16);
            }
        }
        __syncthreads();   // bas/fg/efs reads done -> union may be overwritten

        // ---- stage 4a: write tmp (pair-swizzled) and H hi/lo planes ----
        {
            int e = t >> 3, mg = t & 7;
            #pragma unroll
            for (int mm = 0; mm < 4; mm++) {
                int m = mg * 4 + mm, mp = m >> 1;
                #pragma unroll
                for (int d = 0; d < 3; d++)
                    tmpf[e * 96 + d * 32 + (((mp ^ (e & 7)) << 1) | (m & 1))] = tv[mm * 3 + d];
            }
        }
        {
            int e = lane, jg = w;
            int off = e * 128 + ((jg ^ (e & 7)) << 4);
            *(uint4*)(smc + SM_HHI + off) = make_uint4(hip[0], hip[1], hip[2], hip[3]);
            *(uint4*)(smc + SM_HLO + off) = make_uint4(lop[0], lop[1], lop[2], lop[3]);
        }
        __syncthreads();

        // ---- stage 4b: HMMA GEMM (3-term bf16 split), warp w owns o=[96w,96w+96) ----
        float D[2][12][4];
        #pragma unroll
        for (int nb = 0; nb < 12; nb++) {
            float2 bb = __ldg((const float2*)(b2 + w * 96 + nb * 8 + tig * 2));
            #pragma unroll
            for (int eb = 0; eb < 2; eb++) {
                D[eb][nb][0] = bb.x; D[eb][nb][1] = bb.y;
                D[eb][nb][2] = bb.x; D[eb][nb][3] = bb.y;
            }
        }
        {
            unsigned browoff = (unsigned)((w * 96 + bnb * 8 + brow) * 128);
            #pragma unroll
            for (int K = 0; K < 4; K++) {
                unsigned ah[2][4], al[2][4];
                #pragma unroll
                for (int eb = 0; eb < 2; eb++) {
                    unsigned rowoff = (unsigned)((eb * 16 + arow) * 128);
                    unsigned oct = (unsigned)(((2 * K + ahalf) ^ (lane & 7)) << 4);
                    ldsm_x4(ah[eb], sbase + SM_HHI + rowoff + oct);
                    ldsm_x4(al[eb], sbase + SM_HLO + rowoff + oct);
                }
                unsigned octb = (unsigned)(((2 * K + bhalf) ^ brow) << 4);
                #pragma unroll
                for (int pr = 0; pr < 6; pr++) {
                    unsigned off = browoff + (unsigned)(pr * 2048) + octb;  // 16 rows*128B
                    unsigned bh[4], bl[4];
                    ldsm_x4(bh, sbase + SM_W2HI + off);
                    ldsm_x4(bl, sbase + SM_W2LO + off);
                    #pragma unroll
                    for (int eb = 0; eb < 2; eb++) {
                        mma_bf16(D[eb][2 * pr],     ah[eb], bh[0], bh[1]);
                        mma_bf16(D[eb][2 * pr],     al[eb], bh[0], bh[1]);
                        mma_bf16(D[eb][2 * pr],     ah[eb], bl[0], bl[1]);
                        mma_bf16(D[eb][2 * pr + 1], ah[eb], bh[2], bh[3]);
                        mma_bf16(D[eb][2 * pr + 1], al[eb], bh[2], bh[3]);
                        mma_bf16(D[eb][2 * pr + 1], ah[eb], bl[2], bl[3]);
                    }
                }
            }
        }

        // ---- issue prefetch part B for next tile (gathered f; srcs arrived) ----
        #pragma unroll
        for (int r = 0; r < 6; r++) {
            int idx = t + 256 * r;
            nfg[r] = __ldg(&f[nsrcv[r] * 48 + idx % 48]);
        }

        // ---- epilogue: conv[e][c][d] = sum_m rw[e][c][m]*tmp[e][m][d] ----
        float pc[2][2][3][3];   // [eb][h][ci][d]
        #pragma unroll
        for (int eb = 0; eb < 2; eb++)
            #pragma unroll
            for (int h = 0; h < 2; h++) {
                int e_l = eb * 16 + h * 8 + gid;       // e&7 == gid
                unsigned long long tp[3][4];
                #pragma unroll
                for (int d = 0; d < 3; d++)
                    #pragma unroll
                    for (int j = 0; j < 4; j++) {
                        int mp = j * 4 + tig;
                        tp[d][j] = *(const unsigned long long*)
                            (tmpf + e_l * 96 + d * 32 + ((mp ^ gid) << 1));
                    }
                unsigned long long acc[3][3];
                #pragma unroll
                for (int ci = 0; ci < 3; ci++)
                    #pragma unroll
                    for (int d = 0; d < 3; d++)
                        acc[ci][d] = 0ull;
                #pragma unroll
                for (int ci = 0; ci < 3; ci++)
                    #pragma unroll
                    for (int j = 0; j < 4; j++) {
                        unsigned long long pd;
                        PACK_F32X2(pd, D[eb][ci * 4 + j][h * 2], D[eb][ci * 4 + j][h * 2 + 1]);
                        #pragma unroll
                        for (int d = 0; d < 3; d++)
                            FMA_F32X2(acc[ci][d], pd, tp[d][j]);
                    }
                #pragma unroll
                for (int ci = 0; ci < 3; ci++)
                    #pragma unroll
                    for (int d = 0; d < 3; d++)
                        pc[eb][h][ci][d] = __uint_as_float((unsigned)acc[ci][d])
                                         + __uint_as_float((unsigned)(acc[ci][d] >> 32));
            }
        // reduce m-partials across tig (lane bits 0-1)
        #pragma unroll
        for (int off = 1; off < 4; off <<= 1)
            #pragma unroll
            for (int eb = 0; eb < 2; eb++)
                #pragma unroll
                for (int h = 0; h < 2; h++)
                    #pragma unroll
                    for (int ci = 0; ci < 3; ci++)
                        #pragma unroll
                        for (int d = 0; d < 3; d++)
                            pc[eb][h][ci][d] += __shfl_xor_sync(0xffffffffu, pc[eb][h][ci][d], off);
        __syncthreads();   // ALL tmp reads complete before conv overwrites union
        if (tig == 0) {
            #pragma unroll
            for (int eb = 0; eb < 2; eb++)
                #pragma unroll
                for (int h = 0; h < 2; h++) {
                    int e_l = eb * 16 + h * 8 + gid;
                    #pragma unroll
                    for (int ci = 0; ci < 3; ci++) {
                        int c = w * 3 + ci;
                        #pragma unroll
                        for (int d = 0; d < 3; d++)
                            conv[e_l * 72 + c * 3 + d] = pc[eb][h][ci][d];
                    }
                }
        }
        __syncthreads();

        // ---- stage 5: attention scores, exp, denom atomics, stash v ----
        {
            int e = t >> 3, s = t & 7;
            int ge = eg0 + e;
            if (ge < E) {
                if (s < 4) {
                    float sc = 0.f;
                    #pragma unroll
                    for (int hd = 0; hd < 6; hd++)
                        sc += conv[e * 72 + s * 6 + hd] * conv[e * 72 + 24 + s * 6 + hd];
                    sc *= 0.20412414523193154f;           // 24^-0.5
                    sc = (sc >= 0.f) ? sc : 0.2f * sc;    // leaky_relu(0.2)
                    float ex = __expf(sc);                // shift-invariant softmax
                    g_ex[ge * 4 + s] = ex;
                    atomicAdd(&g_denom[dsts[e] * 4 + s], ex);
                }
                #pragma unroll
                for (int jj = 0; jj < 3; jj++)
                    g_v[ge * 24 + s * 3 + jj] = conv[e * 72 + 48 + s * 3 + jj];
            }
        }
        __syncthreads();
    }
}

__global__ void initK(float* __restrict__ out, int N)
{
    int i = blockIdx.x * blockDim.x + threadIdx.x;
    if (i < N * 24) out[i] = 0.f;
    if (i < N * 4)  g_denom[i] = 0.f;
}

__global__ __launch_bounds__(256)
void passB(const int* __restrict__ dst, float* __restrict__ out, int E)
{
    int idx = blockIdx.x * blockDim.x + threadIdx.x;
    int e = idx >> 3, s = idx & 7;      // 8 threads/edge, 3 outputs each
    if (e >= E) return;
    int d = dst[e];
    int head = s >> 1;                   // 6 floats/head, 3 per thread
    float wgt = g_ex[e * 4 + head] / g_denom[d * 4 + head];
    #pragma unroll
    for (int jj = 0; jj < 3; jj++) {
        int j = s * 3 + jj;
        atomicAdd(&out[d * 24 + j], wgt * g_v[e * 24 + j]);
    }
}

extern "C" void kernel_launch(void* const* d_in, const int* in_sizes, int n_in,
                              void* d_out, int out_size)
{
    const int*   src   = (const int*)d_in[0];
    const int*   dst   = (const int*)d_in[1];
    const float* basis = (const float*)d_in[2];
    const float* efeat = (const float*)d_in[3];
    const float* f     = (const float*)d_in[4];
    const float* W1    = (const float*)d_in[5];
    const float* b1    = (const float*)d_in[6];
    const float* W2    = (const float*)d_in[7];
    const float* b2    = (const float*)d_in[8];
    float* out = (float*)d_out;

    int E = in_sizes[0];          // 160000
    int N = in_sizes[4] / 48;     // f is (N,16,3) -> 10000

    cudaFuncSetAttribute(passA, cudaFuncAttributeMaxDynamicSharedMemorySize, SMEM_BYTES);

    initK<<<(N * 24 + 255) / 256, 256>>>(out, N);

    int ntiles = (E + 31) / 32;
    int grid = ntiles < 148 ? ntiles : 148;
    passA<<<grid, NTHR, SMEM_BYTES>>>(src, dst, basis, efeat, f, W1, b1, W2, b2, E);

    passB<<<(E * 8 + 255) / 256, 256>>>(dst, out, E);
}